// round 4
// baseline (speedup 1.0000x reference)
#include <cuda_runtime.h>
#include <cstdint>
#include <math.h>

#define NTOK 4096
#define EMB  1024
#define HID  2816
#define NE   8
#define MAXPAD 9216

// ===================== device scratch =====================
__device__ int   g_cnt[NE];
__device__ int   g_offp[NE];
__device__ int   g_tok[NE][NTOK];
__device__ float g_gate[NE][NTOK];

__device__ float g_xp[(size_t)MAXPAD * EMB];      // gathered tokens, tf32-rounded
__device__ float g_h [(size_t)MAXPAD * HID];      // SwiGLU intermediate, tf32-rounded
__device__ float g_w1r[(size_t)NE * EMB * HID];   // tf32-rounded weights
__device__ float g_w3r[(size_t)NE * EMB * HID];
__device__ float g_w2r[(size_t)NE * HID * EMB];

// ===================== helpers =====================
__device__ __forceinline__ uint32_t tf32r(float f) {
    uint32_t u;
    asm("cvt.rna.tf32.f32 %0, %1;" : "=r"(u) : "f"(f));
    return u;
}
__device__ __forceinline__ void mma8(float* c, const uint32_t* a, const uint32_t* b) {
    asm volatile("mma.sync.aligned.m16n8k8.row.col.f32.tf32.tf32.f32 "
        "{%0,%1,%2,%3}, {%4,%5,%6,%7}, {%8,%9}, {%0,%1,%2,%3};"
        : "+f"(c[0]), "+f"(c[1]), "+f"(c[2]), "+f"(c[3])
        : "r"(a[0]), "r"(a[1]), "r"(a[2]), "r"(a[3]), "r"(b[0]), "r"(b[1]));
}
__device__ __forceinline__ uint32_t s2u(const void* p) {
    uint32_t a;
    asm("{ .reg .u64 t; cvta.to.shared.u64 t, %1; cvt.u32.u64 %0, t; }" : "=r"(a) : "l"(p));
    return a;
}
__device__ __forceinline__ void cp16(uint32_t dst, const void* src) {
    asm volatile("cp.async.cg.shared.global [%0], [%1], 16;" :: "r"(dst), "l"(src));
}
#define CP_COMMIT() asm volatile("cp.async.commit_group;" ::: "memory")

// ===================== fused round (w1,w3,w2) + cnt reset =====================
__global__ void k_round_all(const float4* __restrict__ w1,
                            const float4* __restrict__ w3,
                            const float4* __restrict__ w2) {
    int which = blockIdx.y;
    const float4* src = (which == 0) ? w1 : (which == 1) ? w3 : w2;
    float4* dst = (which == 0) ? (float4*)g_w1r : (which == 1) ? (float4*)g_w3r : (float4*)g_w2r;
    size_t i = (size_t)blockIdx.x * blockDim.x + threadIdx.x;
    float4 v = src[i];
    v.x = __uint_as_float(tf32r(v.x));
    v.y = __uint_as_float(tf32r(v.y));
    v.z = __uint_as_float(tf32r(v.z));
    v.w = __uint_as_float(tf32r(v.w));
    dst[i] = v;
    if (which == 0 && blockIdx.x == 0 && threadIdx.x < NE) g_cnt[threadIdx.x] = 0;
}

// ===================== router =====================
__global__ void k_router(const float* __restrict__ x, const float* __restrict__ wr) {
    int t    = blockIdx.x * (blockDim.x >> 5) + (threadIdx.x >> 5);
    int lane = threadIdx.x & 31;
    if (t >= NTOK) return;
    const float* xr = x + (size_t)t * EMB;
    float acc[NE];
#pragma unroll
    for (int e = 0; e < NE; e++) acc[e] = 0.f;
    for (int i = lane; i < EMB; i += 32) {
        float xv = xr[i];
#pragma unroll
        for (int e = 0; e < NE; e++) acc[e] += xv * wr[i * NE + e];
    }
#pragma unroll
    for (int e = 0; e < NE; e++)
#pragma unroll
        for (int o = 16; o > 0; o >>= 1) acc[e] += __shfl_xor_sync(0xffffffffu, acc[e], o);
    if (lane == 0) {
        int i0 = 0; float v0 = acc[0];
#pragma unroll
        for (int e = 1; e < NE; e++) if (acc[e] > v0) { v0 = acc[e]; i0 = e; }
        int i1 = -1; float v1 = -3.4e38f;
#pragma unroll
        for (int e = 0; e < NE; e++) if (e != i0 && acc[e] > v1) { v1 = acc[e]; i1 = e; }
        float z  = expf(v1 - v0);
        float p0 = 1.f / (1.f + z);
        float p1 = z  / (1.f + z);
        int s0 = atomicAdd(&g_cnt[i0], 1);
        g_tok[i0][s0] = t; g_gate[i0][s0] = p0;
        int s1 = atomicAdd(&g_cnt[i1], 1);
        g_tok[i1][s1] = t; g_gate[i1][s1] = p1;
    }
}

__global__ void k_prefix() {
    if (threadIdx.x == 0) {
        int op = 0;
        for (int e = 0; e < NE; e++) { g_offp[e] = op; op += (g_cnt[e] + 127) & ~127; }
    }
}

__global__ void k_gather(const float* __restrict__ x) {
    int e = blockIdx.y; int cnt = g_cnt[e];
    int m0 = blockIdx.x * 128;
    if (m0 >= cnt) return;
    int tid = threadIdx.x;
    float* dst = g_xp + (size_t)(g_offp[e] + m0) * EMB;
    for (int id = tid; id < 128 * 256; id += 256) {
        int r = id >> 8, j = id & 255;
        int gm = m0 + r;
        float4 v = make_float4(0.f, 0.f, 0.f, 0.f);
        if (gm < cnt) {
            v = ((const float4*)(x + (size_t)g_tok[e][gm] * EMB))[j];
            v.x = __uint_as_float(tf32r(v.x));
            v.y = __uint_as_float(tf32r(v.y));
            v.z = __uint_as_float(tf32r(v.z));
            v.w = __uint_as_float(tf32r(v.w));
        }
        ((float4*)(dst + (size_t)r * EMB))[j] = v;
    }
}

// ===================== GEMM1: H = silu(X@W1)*(X@W3) =====================
#define A_F   4608            // 128*36 floats (pad 4)
#define B_F   4224            // 32*132 floats (pad 4)
#define ST1F  (A_F + 2*B_F)   // 13056 floats
#define STG1  3
#define KB1   (EMB/32)

__global__ void __launch_bounds__(256, 1) k_mma1() {
    extern __shared__ float sm[];
    int e = blockIdx.z;
    int cnt = g_cnt[e];
    int m0 = blockIdx.y * 128;
    if (m0 >= cnt) return;
    int n0 = blockIdx.x * 128;
    int tid = threadIdx.x, lane = tid & 31, wid = tid >> 5;
    int wm = wid >> 2, wn = wid & 3;
    int grp = lane >> 2, q = lane & 3;
    uint32_t sbase = s2u(sm);
    int ho = g_offp[e] + m0;

    const float* gA  = g_xp  + (size_t)ho * EMB;
    const float* gB1 = g_w1r + (size_t)e * EMB * HID + n0;
    const float* gB3 = g_w3r + (size_t)e * EMB * HID + n0;

    auto load_stage = [&](int kb, int s) {
        uint32_t st = sbase + (uint32_t)s * ST1F * 4;
        int k0 = kb * 32;
#pragma unroll
        for (int it = 0; it < 4; it++) {
            int id = it * 256 + tid;
            int r = id >> 3, c = id & 7;
            cp16(st + (uint32_t)(r * 36 + c * 4) * 4, gA + (size_t)r * EMB + k0 + c * 4);
        }
#pragma unroll
        for (int it = 0; it < 4; it++) {
            int id = it * 256 + tid;
            int k = id >> 5, c = id & 31;
            uint32_t so = (uint32_t)(k * 132 + c * 4) * 4;
            cp16(st + A_F * 4 + so,         gB1 + (size_t)(k0 + k) * HID + c * 4);
            cp16(st + (A_F + B_F) * 4 + so, gB3 + (size_t)(k0 + k) * HID + c * 4);
        }
        CP_COMMIT();
    };

    float accZ[4][4][4], accG[4][4][4];
#pragma unroll
    for (int i = 0; i < 4; i++)
#pragma unroll
        for (int j = 0; j < 4; j++)
#pragma unroll
            for (int r = 0; r < 4; r++) { accZ[i][j][r] = 0.f; accG[i][j][r] = 0.f; }

    load_stage(0, 0);
    load_stage(1, 1);

    for (int kb = 0; kb < KB1; kb++) {
        asm volatile("cp.async.wait_group 1;" ::: "memory");
        __syncthreads();
        const float* st  = sm + (kb % STG1) * ST1F;
        const float* sA  = st;
        const float* sB1 = st + A_F;
        const float* sB3 = st + A_F + B_F;
#pragma unroll
        for (int ks = 0; ks < 4; ks++) {
            int kk = ks * 8;
            uint32_t a[4][4];
#pragma unroll
            for (int i = 0; i < 4; i++) {
                int r = wm * 64 + i * 16 + grp;
                a[i][0] = __float_as_uint(sA[r * 36 + kk + q]);
                a[i][1] = __float_as_uint(sA[(r + 8) * 36 + kk + q]);
                a[i][2] = __float_as_uint(sA[r * 36 + kk + 4 + q]);
                a[i][3] = __float_as_uint(sA[(r + 8) * 36 + kk + 4 + q]);
            }
            uint32_t b1[4][2], b3[4][2];
#pragma unroll
            for (int j = 0; j < 4; j++) {
                int c = wn * 32 + j * 8 + grp;
                b1[j][0] = __float_as_uint(sB1[(kk + q) * 132 + c]);
                b1[j][1] = __float_as_uint(sB1[(kk + 4 + q) * 132 + c]);
                b3[j][0] = __float_as_uint(sB3[(kk + q) * 132 + c]);
                b3[j][1] = __float_as_uint(sB3[(kk + 4 + q) * 132 + c]);
            }
#pragma unroll
            for (int i = 0; i < 4; i++)
#pragma unroll
                for (int j = 0; j < 4; j++) {
                    mma8(accZ[i][j], a[i], b1[j]);
                    mma8(accG[i][j], a[i], b3[j]);
                }
        }
        if (kb + 2 < KB1) load_stage(kb + 2, (kb + 2) % STG1);
        else CP_COMMIT();
    }

    float* gH = g_h + (size_t)ho * HID + n0;
#pragma unroll
    for (int i = 0; i < 4; i++) {
        int r = wm * 64 + i * 16 + grp;
#pragma unroll
        for (int j = 0; j < 4; j++) {
            int c = wn * 32 + j * 8 + 2 * q;
            float h[4];
#pragma unroll
            for (int t2 = 0; t2 < 4; t2++) {
                float z = accZ[i][j][t2];
                float g = accG[i][j][t2];
                float s = z / (1.f + __expf(-z));
                h[t2] = __uint_as_float(tf32r(s * g));
            }
            *(float2*)(gH + (size_t)r * HID + c)       = make_float2(h[0], h[1]);
            *(float2*)(gH + (size_t)(r + 8) * HID + c) = make_float2(h[2], h[3]);
        }
    }
}

// ===================== GEMM2: out += gate * (H @ W2) =====================
#define ST2F  (A_F + B_F)     // 8832 floats
#define STG2  4
#define KB2   (HID/32)

__global__ void __launch_bounds__(256, 1) k_mma2(float* __restrict__ out) {
    extern __shared__ float sm[];
    int e = blockIdx.z;
    int cnt = g_cnt[e];
    int m0 = blockIdx.y * 128;
    if (m0 >= cnt) return;
    int n0 = blockIdx.x * 128;
    int tid = threadIdx.x, lane = tid & 31, wid = tid >> 5;
    int wm = wid >> 2, wn = wid & 3;
    int grp = lane >> 2, q = lane & 3;
    uint32_t sbase = s2u(sm);
    int ho = g_offp[e] + m0;

    const float* gA = g_h   + (size_t)ho * HID;
    const float* gB = g_w2r + (size_t)e * HID * EMB + n0;

    auto load_stage = [&](int kb, int s) {
        uint32_t st = sbase + (uint32_t)s * ST2F * 4;
        int k0 = kb * 32;
#pragma unroll
        for (int it = 0; it < 4; it++) {
            int id = it * 256 + tid;
            int r = id >> 3, c = id & 7;
            cp16(st + (uint32_t)(r * 36 + c * 4) * 4, gA + (size_t)r * HID + k0 + c * 4);
        }
#pragma unroll
        for (int it = 0; it < 4; it++) {
            int id = it * 256 + tid;
            int k = id >> 5, c = id & 31;
            cp16(st + A_F * 4 + (uint32_t)(k * 132 + c * 4) * 4,
                 gB + (size_t)(k0 + k) * EMB + c * 4);
        }
        CP_COMMIT();
    };

    float acc[4][4][4];
#pragma unroll
    for (int i = 0; i < 4; i++)
#pragma unroll
        for (int j = 0; j < 4; j++)
#pragma unroll
            for (int r = 0; r < 4; r++) acc[i][j][r] = 0.f;

    load_stage(0, 0);
    load_stage(1, 1);
    load_stage(2, 2);

    for (int kb = 0; kb < KB2; kb++) {
        asm volatile("cp.async.wait_group 2;" ::: "memory");
        __syncthreads();
        const float* st = sm + (kb % STG2) * ST2F;
        const float* sA = st;
        const float* sB = st + A_F;
#pragma unroll
        for (int ks = 0; ks < 4; ks++) {
            int kk = ks * 8;
            uint32_t a[4][4];
#pragma unroll
            for (int i = 0; i < 4; i++) {
                int r = wm * 64 + i * 16 + grp;
                a[i][0] = __float_as_uint(sA[r * 36 + kk + q]);
                a[i][1] = __float_as_uint(sA[(r + 8) * 36 + kk + q]);
                a[i][2] = __float_as_uint(sA[r * 36 + kk + 4 + q]);
                a[i][3] = __float_as_uint(sA[(r + 8) * 36 + kk + 4 + q]);
            }
            uint32_t b[4][2];
#pragma unroll
            for (int j = 0; j < 4; j++) {
                int c = wn * 32 + j * 8 + grp;
                b[j][0] = __float_as_uint(sB[(kk + q) * 132 + c]);
                b[j][1] = __float_as_uint(sB[(kk + 4 + q) * 132 + c]);
            }
#pragma unroll
            for (int i = 0; i < 4; i++)
#pragma unroll
                for (int j = 0; j < 4; j++)
                    mma8(acc[i][j], a[i], b[j]);
        }
        if (kb + 3 < KB2) load_stage(kb + 3, (kb + 3) % STG2);
        else CP_COMMIT();
    }

    // epilogue: scatter-accumulate gate*acc directly into out (2 adds/elem, commutative)
#pragma unroll
    for (int i = 0; i < 4; i++) {
        int r = wm * 64 + i * 16 + grp;
        int row0 = m0 + r, row1 = row0 + 8;
        bool act0 = row0 < cnt, act1 = row1 < cnt;
        int   t0 = act0 ? g_tok[e][row0] : 0;
        int   t1 = act1 ? g_tok[e][row1] : 0;
        float gt0 = act0 ? g_gate[e][row0] : 0.f;
        float gt1 = act1 ? g_gate[e][row1] : 0.f;
        float* o0 = out + (size_t)t0 * EMB + n0;
        float* o1 = out + (size_t)t1 * EMB + n0;
#pragma unroll
        for (int j = 0; j < 4; j++) {
            int c = wn * 32 + j * 8 + 2 * q;
            if (act0) {
                atomicAdd(&o0[c],     gt0 * acc[i][j][0]);
                atomicAdd(&o0[c + 1], gt0 * acc[i][j][1]);
            }
            if (act1) {
                atomicAdd(&o1[c],     gt1 * acc[i][j][2]);
                atomicAdd(&o1[c + 1], gt1 * acc[i][j][3]);
            }
        }
    }
}

// ===================== launcher =====================
extern "C" void kernel_launch(void* const* d_in, const int* in_sizes, int n_in,
                              void* d_out, int out_size) {
    const float* x  = (const float*)d_in[0];
    const float* wr = (const float*)d_in[1];
    const float* w1 = (const float*)d_in[2];
    const float* w3 = (const float*)d_in[3];
    const float* w2 = (const float*)d_in[4];
    float* out = (float*)d_out;

    const int SM1 = STG1 * ST1F * 4;   // 156672
    const int SM2 = STG2 * ST2F * 4;   // 141312
    cudaFuncSetAttribute(k_mma1, cudaFuncAttributeMaxDynamicSharedMemorySize, SM1);
    cudaFuncSetAttribute(k_mma2, cudaFuncAttributeMaxDynamicSharedMemorySize, SM2);

    cudaMemsetAsync(out, 0, (size_t)out_size * sizeof(float));

    const int N4 = NE * EMB * HID / 4;
    k_round_all<<<dim3(N4 / 256, 3), 256>>>((const float4*)w1, (const float4*)w3,
                                            (const float4*)w2);
    k_router<<<NTOK / 8, 256>>>(x, wr);
    k_prefix<<<1, 1>>>();
    k_gather<<<dim3(NTOK / 128, NE), 256>>>(x);

    k_mma1<<<dim3(HID / 128, NTOK / 128, NE), 256, SM1>>>();
    k_mma2<<<dim3(EMB / 128, NTOK / 128, NE), 256, SM2>>>(out);
}

// round 5
// speedup vs baseline: 1.5201x; 1.5201x over previous
#include <cuda_runtime.h>
#include <cuda_fp16.h>
#include <cstdint>
#include <math.h>

#define NTOK 4096
#define EMB  1024
#define HID  2816
#define NE   8
#define MAXPAD 9216

// ===================== device scratch =====================
__device__ int   g_cnt[NE];
__device__ int   g_tok[NE][NTOK];
__device__ float g_gate[NE][NTOK];

__device__ __half g_xp[(size_t)MAXPAD * EMB];      // gathered tokens fp16
__device__ __half g_h [(size_t)MAXPAD * HID];      // SwiGLU intermediate fp16
__device__ __half g_w1h[(size_t)NE * HID * EMB];   // fp16, transposed [e][n][k]
__device__ __half g_w3h[(size_t)NE * HID * EMB];
__device__ __half g_w2h[(size_t)NE * EMB * HID];   // [e][n=EMB][k=HID]

// ===================== helpers =====================
__device__ __forceinline__ void mma16(float* c, const uint32_t* a, const uint32_t* b) {
    asm volatile("mma.sync.aligned.m16n8k16.row.col.f32.f16.f16.f32 "
        "{%0,%1,%2,%3}, {%4,%5,%6,%7}, {%8,%9}, {%0,%1,%2,%3};"
        : "+f"(c[0]), "+f"(c[1]), "+f"(c[2]), "+f"(c[3])
        : "r"(a[0]), "r"(a[1]), "r"(a[2]), "r"(a[3]), "r"(b[0]), "r"(b[1]));
}
__device__ __forceinline__ uint32_t s2u(const void* p) {
    uint32_t a;
    asm("{ .reg .u64 t; cvta.to.shared.u64 t, %1; cvt.u32.u64 %0, t; }" : "=r"(a) : "l"(p));
    return a;
}
__device__ __forceinline__ void cp16(uint32_t dst, const void* src) {
    asm volatile("cp.async.cg.shared.global [%0], [%1], 16;" :: "r"(dst), "l"(src));
}
#define CP_COMMIT() asm volatile("cp.async.commit_group;" ::: "memory")

__device__ __forceinline__ int offp_of(int e) {
    int o = 0;
    for (int i = 0; i < NE; i++) if (i < e) o += (g_cnt[i] + 127) & ~127;
    return o;
}

// ===== fused: fp16-convert + transpose weights to [e][n][k], reset cnt =====
// grid (88, 32, 3*NE), block (32,8)
__global__ void k_roundT(const float* __restrict__ w1,
                         const float* __restrict__ w3,
                         const float* __restrict__ w2) {
    __shared__ float t[32][33];
    int which = blockIdx.z / NE, e = blockIdx.z % NE;
    if (which == 0 && blockIdx.x == 0 && blockIdx.y == 0 &&
        threadIdx.y == 0 && threadIdx.x < NE) g_cnt[threadIdx.x] = 0;

    const float* in; __half* outp; int K, N, nt, kt;
    if (which < 2) {                 // w1/w3: [k=EMB][n=HID] -> [n][k]
        in = ((which == 0) ? w1 : w3) + (size_t)e * EMB * HID;
        outp = ((which == 0) ? g_w1h : g_w3h) + (size_t)e * HID * EMB;
        K = EMB; N = HID; nt = blockIdx.x; kt = blockIdx.y;
    } else {                         // w2: [k=HID][n=EMB] -> [n][k]
        in = w2 + (size_t)e * HID * EMB;
        outp = g_w2h + (size_t)e * EMB * HID;
        K = HID; N = EMB; kt = blockIdx.x; nt = blockIdx.y;
    }
    int tx = threadIdx.x, ty = threadIdx.y;
#pragma unroll
    for (int i = 0; i < 4; i++)
        t[ty + 8 * i][tx] = in[(size_t)(kt * 32 + ty + 8 * i) * N + nt * 32 + tx];
    __syncthreads();
#pragma unroll
    for (int i = 0; i < 4; i++)
        outp[(size_t)(nt * 32 + ty + 8 * i) * K + kt * 32 + tx] =
            __float2half_rn(t[tx][ty + 8 * i]);
}

// ===================== router =====================
__global__ void k_router(const float* __restrict__ x, const float* __restrict__ wr) {
    int t    = blockIdx.x * (blockDim.x >> 5) + (threadIdx.x >> 5);
    int lane = threadIdx.x & 31;
    if (t >= NTOK) return;
    const float* xr = x + (size_t)t * EMB;
    float acc[NE];
#pragma unroll
    for (int e = 0; e < NE; e++) acc[e] = 0.f;
    for (int i = lane; i < EMB; i += 32) {
        float xv = xr[i];
#pragma unroll
        for (int e = 0; e < NE; e++) acc[e] += xv * wr[i * NE + e];
    }
#pragma unroll
    for (int e = 0; e < NE; e++)
#pragma unroll
        for (int o = 16; o > 0; o >>= 1) acc[e] += __shfl_xor_sync(0xffffffffu, acc[e], o);
    if (lane == 0) {
        int i0 = 0; float v0 = acc[0];
#pragma unroll
        for (int e = 1; e < NE; e++) if (acc[e] > v0) { v0 = acc[e]; i0 = e; }
        int i1 = -1; float v1 = -3.4e38f;
#pragma unroll
        for (int e = 0; e < NE; e++) if (e != i0 && acc[e] > v1) { v1 = acc[e]; i1 = e; }
        float z  = expf(v1 - v0);
        float p0 = 1.f / (1.f + z);
        float p1 = z  / (1.f + z);
        int s0 = atomicAdd(&g_cnt[i0], 1);
        g_tok[i0][s0] = t; g_gate[i0][s0] = p0;
        int s1 = atomicAdd(&g_cnt[i1], 1);
        g_tok[i1][s1] = t; g_gate[i1][s1] = p1;
    }
}

// ===================== gather -> fp16 ====================
// grid (NTOK/16, NE), 256 threads; 16 rows per block
__global__ void k_gather(const float* __restrict__ x) {
    int e = blockIdx.y; int cnt = g_cnt[e];
    int m0 = blockIdx.x * 16;
    int padded = (cnt + 127) & ~127;
    if (m0 >= padded) return;
    __half* dst = g_xp + (size_t)(offp_of(e) + m0) * EMB;
    for (int idx = threadIdx.x; idx < 16 * 128; idx += 256) {
        int r = idx >> 7, j = idx & 127;   // j indexes 8-float groups
        int gm = m0 + r;
        uint4 o = make_uint4(0, 0, 0, 0);
        if (gm < cnt) {
            const float4* src = (const float4*)(x + (size_t)g_tok[e][gm] * EMB) + j * 2;
            float4 v0 = src[0], v1 = src[1];
            __half2 h0 = __floats2half2_rn(v0.x, v0.y);
            __half2 h1 = __floats2half2_rn(v0.z, v0.w);
            __half2 h2 = __floats2half2_rn(v1.x, v1.y);
            __half2 h3 = __floats2half2_rn(v1.z, v1.w);
            o = make_uint4(*(uint32_t*)&h0, *(uint32_t*)&h1,
                           *(uint32_t*)&h2, *(uint32_t*)&h3);
        }
        ((uint4*)(dst + (size_t)r * EMB))[j] = o;
    }
}

// ===================== GEMM1: H = silu(X@W1)*(X@W3) =====================
// 128x128x32 tiles, 8 warps (2x4), warp 64x32, m16n8k16 fp16
#define AK    40                       // smem row stride in halves (32 + 8 pad)
#define TILE_H (128 * AK)              // 5120 halves = 10240 B
#define ST1H  (3 * TILE_H)
#define STG1  4
#define KB1   (EMB / 32)

__global__ void __launch_bounds__(256, 1) k_mma1() {
    extern __shared__ __half smh[];
    int e = blockIdx.z;
    int cnt = g_cnt[e];
    int m0 = blockIdx.y * 128;
    if (m0 >= cnt) return;
    int n0 = blockIdx.x * 128;
    int tid = threadIdx.x, lane = tid & 31, wid = tid >> 5;
    int wm = wid >> 2, wn = wid & 3;
    int grp = lane >> 2, q = lane & 3;
    uint32_t sbase = s2u(smh);
    int ho = offp_of(e) + m0;

    const __half* gA  = g_xp  + (size_t)ho * EMB;
    const __half* gB1 = g_w1h + ((size_t)e * HID + n0) * EMB;
    const __half* gB3 = g_w3h + ((size_t)e * HID + n0) * EMB;

    auto load_stage = [&](int kb, int s) {
        uint32_t st = sbase + (uint32_t)s * ST1H * 2;
        int k0 = kb * 32;
#pragma unroll
        for (int it = 0; it < 2; it++) {
            int id = it * 256 + tid;
            int r = id >> 2, c = id & 3;
            uint32_t so = (uint32_t)(r * AK) * 2 + c * 16;
            const size_t go = (size_t)r * EMB + k0 + c * 8;
            cp16(st + so,                gA  + go);
            cp16(st + TILE_H * 2 + so,   gB1 + go);
            cp16(st + TILE_H * 4 + so,   gB3 + go);
        }
        CP_COMMIT();
    };

    float accZ[4][4][4], accG[4][4][4];
#pragma unroll
    for (int i = 0; i < 4; i++)
#pragma unroll
        for (int j = 0; j < 4; j++)
#pragma unroll
            for (int r = 0; r < 4; r++) { accZ[i][j][r] = 0.f; accG[i][j][r] = 0.f; }

    load_stage(0, 0);
    load_stage(1, 1);
    load_stage(2, 2);

    for (int kb = 0; kb < KB1; kb++) {
        asm volatile("cp.async.wait_group 2;" ::: "memory");
        __syncthreads();
        const __half* st  = smh + (size_t)(kb % STG1) * ST1H;
        const __half* sA  = st;
        const __half* sB1 = st + TILE_H;
        const __half* sB3 = st + 2 * TILE_H;
#pragma unroll
        for (int ks = 0; ks < 2; ks++) {
            int kk = ks * 16 + 2 * q;
            uint32_t a[4][4];
#pragma unroll
            for (int i = 0; i < 4; i++) {
                int r = wm * 64 + i * 16 + grp;
                a[i][0] = *(const uint32_t*)(sA + r * AK + kk);
                a[i][1] = *(const uint32_t*)(sA + (r + 8) * AK + kk);
                a[i][2] = *(const uint32_t*)(sA + r * AK + kk + 8);
                a[i][3] = *(const uint32_t*)(sA + (r + 8) * AK + kk + 8);
            }
            uint32_t b1[4][2], b3[4][2];
#pragma unroll
            for (int j = 0; j < 4; j++) {
                int c = wn * 32 + j * 8 + grp;
                b1[j][0] = *(const uint32_t*)(sB1 + c * AK + kk);
                b1[j][1] = *(const uint32_t*)(sB1 + c * AK + kk + 8);
                b3[j][0] = *(const uint32_t*)(sB3 + c * AK + kk);
                b3[j][1] = *(const uint32_t*)(sB3 + c * AK + kk + 8);
            }
#pragma unroll
            for (int i = 0; i < 4; i++)
#pragma unroll
                for (int j = 0; j < 4; j++) {
                    mma16(accZ[i][j], a[i], b1[j]);
                    mma16(accG[i][j], a[i], b3[j]);
                }
        }
        if (kb + 3 < KB1) load_stage(kb + 3, (kb + 3) % STG1);
        else CP_COMMIT();
    }

    __half* gH = g_h + (size_t)ho * HID + n0;
#pragma unroll
    for (int i = 0; i < 4; i++) {
        int r = wm * 64 + i * 16 + grp;
#pragma unroll
        for (int j = 0; j < 4; j++) {
            int c = wn * 32 + j * 8 + 2 * q;
            float h[4];
#pragma unroll
            for (int t2 = 0; t2 < 4; t2++) {
                float z = accZ[i][j][t2];
                float g = accG[i][j][t2];
                h[t2] = (z / (1.f + __expf(-z))) * g;
            }
            __half2 lo = __floats2half2_rn(h[0], h[1]);
            __half2 hi = __floats2half2_rn(h[2], h[3]);
            *(uint32_t*)(gH + (size_t)r * HID + c)       = *(uint32_t*)&lo;
            *(uint32_t*)(gH + (size_t)(r + 8) * HID + c) = *(uint32_t*)&hi;
        }
    }
}

// ===================== GEMM2: out += gate * (H @ W2) =====================
#define ST2H  (2 * TILE_H)
#define STG2  5
#define KB2   (HID / 32)

__global__ void __launch_bounds__(256, 1) k_mma2(float* __restrict__ out) {
    extern __shared__ __half smh[];
    int e = blockIdx.z;
    int cnt = g_cnt[e];
    int m0 = blockIdx.y * 128;
    if (m0 >= cnt) return;
    int n0 = blockIdx.x * 128;
    int tid = threadIdx.x, lane = tid & 31, wid = tid >> 5;
    int wm = wid >> 2, wn = wid & 3;
    int grp = lane >> 2, q = lane & 3;
    uint32_t sbase = s2u(smh);
    int ho = offp_of(e) + m0;

    const __half* gA = g_h   + (size_t)ho * HID;
    const __half* gB = g_w2h + ((size_t)e * EMB + n0) * HID;

    auto load_stage = [&](int kb, int s) {
        uint32_t st = sbase + (uint32_t)s * ST2H * 2;
        int k0 = kb * 32;
#pragma unroll
        for (int it = 0; it < 2; it++) {
            int id = it * 256 + tid;
            int r = id >> 2, c = id & 3;
            uint32_t so = (uint32_t)(r * AK) * 2 + c * 16;
            const size_t go = (size_t)r * HID + k0 + c * 8;
            cp16(st + so,              gA + go);
            cp16(st + TILE_H * 2 + so, gB + go);
        }
        CP_COMMIT();
    };

    float acc[4][4][4];
#pragma unroll
    for (int i = 0; i < 4; i++)
#pragma unroll
        for (int j = 0; j < 4; j++)
#pragma unroll
            for (int r = 0; r < 4; r++) acc[i][j][r] = 0.f;

    load_stage(0, 0);
    load_stage(1, 1);
    load_stage(2, 2);
    load_stage(3, 3);

    for (int kb = 0; kb < KB2; kb++) {
        asm volatile("cp.async.wait_group 3;" ::: "memory");
        __syncthreads();
        const __half* st = smh + (size_t)(kb % STG2) * ST2H;
        const __half* sA = st;
        const __half* sB = st + TILE_H;
#pragma unroll
        for (int ks = 0; ks < 2; ks++) {
            int kk = ks * 16 + 2 * q;
            uint32_t a[4][4];
#pragma unroll
            for (int i = 0; i < 4; i++) {
                int r = wm * 64 + i * 16 + grp;
                a[i][0] = *(const uint32_t*)(sA + r * AK + kk);
                a[i][1] = *(const uint32_t*)(sA + (r + 8) * AK + kk);
                a[i][2] = *(const uint32_t*)(sA + r * AK + kk + 8);
                a[i][3] = *(const uint32_t*)(sA + (r + 8) * AK + kk + 8);
            }
            uint32_t b[4][2];
#pragma unroll
            for (int j = 0; j < 4; j++) {
                int c = wn * 32 + j * 8 + grp;
                b[j][0] = *(const uint32_t*)(sB + c * AK + kk);
                b[j][1] = *(const uint32_t*)(sB + c * AK + kk + 8);
            }
#pragma unroll
            for (int i = 0; i < 4; i++)
#pragma unroll
                for (int j = 0; j < 4; j++)
                    mma16(acc[i][j], a[i], b[j]);
        }
        if (kb + 4 < KB2) load_stage(kb + 4, (kb + 4) % STG2);
        else CP_COMMIT();
    }

#pragma unroll
    for (int i = 0; i < 4; i++) {
        int r = wm * 64 + i * 16 + grp;
        int row0 = m0 + r, row1 = row0 + 8;
        bool act0 = row0 < cnt, act1 = row1 < cnt;
        int   t0 = act0 ? g_tok[e][row0] : 0;
        int   t1 = act1 ? g_tok[e][row1] : 0;
        float gt0 = act0 ? g_gate[e][row0] : 0.f;
        float gt1 = act1 ? g_gate[e][row1] : 0.f;
        float* o0 = out + (size_t)t0 * EMB + n0;
        float* o1 = out + (size_t)t1 * EMB + n0;
#pragma unroll
        for (int j = 0; j < 4; j++) {
            int c = wn * 32 + j * 8 + 2 * q;
            if (act0) {
                atomicAdd(&o0[c],     gt0 * acc[i][j][0]);
                atomicAdd(&o0[c + 1], gt0 * acc[i][j][1]);
            }
            if (act1) {
                atomicAdd(&o1[c],     gt1 * acc[i][j][2]);
                atomicAdd(&o1[c + 1], gt1 * acc[i][j][3]);
            }
        }
    }
}

// ===================== launcher =====================
extern "C" void kernel_launch(void* const* d_in, const int* in_sizes, int n_in,
                              void* d_out, int out_size) {
    const float* x  = (const float*)d_in[0];
    const float* wr = (const float*)d_in[1];
    const float* w1 = (const float*)d_in[2];
    const float* w3 = (const float*)d_in[3];
    const float* w2 = (const float*)d_in[4];
    float* out = (float*)d_out;

    const int SM1 = STG1 * ST1H * 2;   // 122880
    const int SM2 = STG2 * ST2H * 2;   // 102400
    cudaFuncSetAttribute(k_mma1, cudaFuncAttributeMaxDynamicSharedMemorySize, SM1);
    cudaFuncSetAttribute(k_mma2, cudaFuncAttributeMaxDynamicSharedMemorySize, SM2);

    k_roundT<<<dim3(HID / 32, EMB / 32, 3 * NE), dim3(32, 8)>>>(w1, w3, w2);
    k_router<<<NTOK / 8, 256>>>(x, wr);
    k_gather<<<dim3(NTOK / 16, NE), 256>>>(x);

    k_mma1<<<dim3(HID / 128, NTOK / 128, NE), 256, SM1>>>();

    cudaMemsetAsync(out, 0, (size_t)out_size * sizeof(float));
    k_mma2<<<dim3(EMB / 128, NTOK / 128, NE), 256, SM2>>>(out);
}

// round 7
// speedup vs baseline: 1.5355x; 1.0101x over previous
#include <cuda_runtime.h>
#include <cuda_fp16.h>
#include <cstdint>
#include <math.h>

#define NTOK 4096
#define EMB  1024
#define HID  2816
#define NE   8
#define MAXPAD 9216

// ===================== device scratch =====================
__device__ int   g_cnt[NE];
__device__ int   g_tok[NE][NTOK];
__device__ float g_gate[NE][NTOK];

__device__ __half g_xp[(size_t)MAXPAD * EMB];
__device__ __half g_h [(size_t)MAXPAD * HID];
__device__ __half g_w1h[(size_t)NE * HID * EMB];   // [e][n][k]
__device__ __half g_w3h[(size_t)NE * HID * EMB];
__device__ __half g_w2h[(size_t)NE * EMB * HID];   // [e][n=EMB][k=HID]

// ===================== helpers =====================
__device__ __forceinline__ void mma16(float* c, const uint32_t* a, const uint32_t* b) {
    asm volatile("mma.sync.aligned.m16n8k16.row.col.f32.f16.f16.f32 "
        "{%0,%1,%2,%3}, {%4,%5,%6,%7}, {%8,%9}, {%0,%1,%2,%3};"
        : "+f"(c[0]), "+f"(c[1]), "+f"(c[2]), "+f"(c[3])
        : "r"(a[0]), "r"(a[1]), "r"(a[2]), "r"(a[3]), "r"(b[0]), "r"(b[1]));
}
__device__ __forceinline__ uint32_t s2u(const void* p) {
    uint32_t a;
    asm("{ .reg .u64 t; cvta.to.shared.u64 t, %1; cvt.u32.u64 %0, t; }" : "=r"(a) : "l"(p));
    return a;
}
__device__ __forceinline__ void cp16(uint32_t dst, const void* src) {
    asm volatile("cp.async.cg.shared.global [%0], [%1], 16;" :: "r"(dst), "l"(src));
}
#define CP_COMMIT() asm volatile("cp.async.commit_group;" ::: "memory")

__device__ __forceinline__ int offp_of(int e) {
    int o = 0;
    for (int i = 0; i < NE; i++) if (i < e) o += (g_cnt[i] + 127) & ~127;
    return o;
}

// ===== fused: fp16-convert + transpose weights to [e][n][k], reset cnt =====
__global__ void k_roundT(const float* __restrict__ w1,
                         const float* __restrict__ w3,
                         const float* __restrict__ w2) {
    __shared__ float t[32][33];
    int which = blockIdx.z / NE, e = blockIdx.z % NE;
    if (which == 0 && blockIdx.x == 0 && blockIdx.y == 0 &&
        threadIdx.y == 0 && threadIdx.x < NE) g_cnt[threadIdx.x] = 0;

    const float* in; __half* outp; int K, N, nt, kt;
    if (which < 2) {
        in = ((which == 0) ? w1 : w3) + (size_t)e * EMB * HID;
        outp = ((which == 0) ? g_w1h : g_w3h) + (size_t)e * HID * EMB;
        K = EMB; N = HID; nt = blockIdx.x; kt = blockIdx.y;
    } else {
        in = w2 + (size_t)e * HID * EMB;
        outp = g_w2h + (size_t)e * EMB * HID;
        K = HID; N = EMB; kt = blockIdx.x; nt = blockIdx.y;
    }
    int tx = threadIdx.x, ty = threadIdx.y;
#pragma unroll
    for (int i = 0; i < 4; i++)
        t[ty + 8 * i][tx] = in[(size_t)(kt * 32 + ty + 8 * i) * N + nt * 32 + tx];
    __syncthreads();
#pragma unroll
    for (int i = 0; i < 4; i++)
        outp[(size_t)(nt * 32 + ty + 8 * i) * K + kt * 32 + tx] =
            __float2half_rn(t[tx][ty + 8 * i]);
}

// ===================== router =====================
__global__ void k_router(const float* __restrict__ x, const float* __restrict__ wr) {
    int t    = blockIdx.x * (blockDim.x >> 5) + (threadIdx.x >> 5);
    int lane = threadIdx.x & 31;
    if (t >= NTOK) return;
    const float* xr = x + (size_t)t * EMB;
    float acc[NE];
#pragma unroll
    for (int e = 0; e < NE; e++) acc[e] = 0.f;
    for (int i = lane; i < EMB; i += 32) {
        float xv = xr[i];
#pragma unroll
        for (int e = 0; e < NE; e++) acc[e] += xv * wr[i * NE + e];
    }
#pragma unroll
    for (int e = 0; e < NE; e++)
#pragma unroll
        for (int o = 16; o > 0; o >>= 1) acc[e] += __shfl_xor_sync(0xffffffffu, acc[e], o);
    if (lane == 0) {
        int i0 = 0; float v0 = acc[0];
#pragma unroll
        for (int e = 1; e < NE; e++) if (acc[e] > v0) { v0 = acc[e]; i0 = e; }
        int i1 = -1; float v1 = -3.4e38f;
#pragma unroll
        for (int e = 0; e < NE; e++) if (e != i0 && acc[e] > v1) { v1 = acc[e]; i1 = e; }
        float z  = expf(v1 - v0);
        float p0 = 1.f / (1.f + z);
        float p1 = z  / (1.f + z);
        int s0 = atomicAdd(&g_cnt[i0], 1);
        g_tok[i0][s0] = t; g_gate[i0][s0] = p0;
        int s1 = atomicAdd(&g_cnt[i1], 1);
        g_tok[i1][s1] = t; g_gate[i1][s1] = p1;
    }
}

// ===================== gather -> fp16 ====================
__global__ void k_gather(const float* __restrict__ x) {
    int e = blockIdx.y; int cnt = g_cnt[e];
    int m0 = blockIdx.x * 16;
    int padded = (cnt + 127) & ~127;
    if (m0 >= padded) return;
    __half* dst = g_xp + (size_t)(offp_of(e) + m0) * EMB;
    for (int idx = threadIdx.x; idx < 16 * 128; idx += 256) {
        int r = idx >> 7, j = idx & 127;
        int gm = m0 + r;
        uint4 o = make_uint4(0, 0, 0, 0);
        if (gm < cnt) {
            const float4* src = (const float4*)(x + (size_t)g_tok[e][gm] * EMB) + j * 2;
            float4 v0 = src[0], v1 = src[1];
            __half2 h0 = __floats2half2_rn(v0.x, v0.y);
            __half2 h1 = __floats2half2_rn(v0.z, v0.w);
            __half2 h2 = __floats2half2_rn(v1.x, v1.y);
            __half2 h3 = __floats2half2_rn(v1.z, v1.w);
            o = make_uint4(*(uint32_t*)&h0, *(uint32_t*)&h1,
                           *(uint32_t*)&h2, *(uint32_t*)&h3);
        }
        ((uint4*)(dst + (size_t)r * EMB))[j] = o;
    }
}

// ===================== GEMM1: H = silu(X@W1)*(X@W3) =====================
// 128x128x32 CTA tile, 16 warps (4x4), warp tile 32x32, m16n8k16 fp16
#define AK    40
#define TILE_H (128 * AK)
#define ST1H  (3 * TILE_H)
#define STG1  4
#define KB1   (EMB / 32)

__global__ void __launch_bounds__(512, 1) k_mma1() {
    extern __shared__ __half smh[];
    int e = blockIdx.z;
    int cnt = g_cnt[e];
    int m0 = blockIdx.y * 128;
    if (m0 >= cnt) return;
    int n0 = blockIdx.x * 128;
    int tid = threadIdx.x, lane = tid & 31, wid = tid >> 5;
    int wm = wid >> 2, wn = wid & 3;
    int grp = lane >> 2, q = lane & 3;
    uint32_t sbase = s2u(smh);
    int ho = offp_of(e) + m0;

    const __half* gA  = g_xp  + (size_t)ho * EMB;
    const __half* gB1 = g_w1h + ((size_t)e * HID + n0) * EMB;
    const __half* gB3 = g_w3h + ((size_t)e * HID + n0) * EMB;

    auto load_stage = [&](int kb, int s) {
        uint32_t st = sbase + (uint32_t)s * ST1H * 2;
        int k0 = kb * 32;
        int r = tid >> 2, c = tid & 3;
        uint32_t so = (uint32_t)(r * AK) * 2 + c * 16;
        const size_t go = (size_t)r * EMB + k0 + c * 8;
        cp16(st + so,              gA  + go);
        cp16(st + TILE_H * 2 + so, gB1 + go);
        cp16(st + TILE_H * 4 + so, gB3 + go);
        CP_COMMIT();
    };

    float accZ[2][4][4], accG[2][4][4];
#pragma unroll
    for (int i = 0; i < 2; i++)
#pragma unroll
        for (int j = 0; j < 4; j++)
#pragma unroll
            for (int r = 0; r < 4; r++) { accZ[i][j][r] = 0.f; accG[i][j][r] = 0.f; }

    load_stage(0, 0);
    load_stage(1, 1);
    load_stage(2, 2);

    for (int kb = 0; kb < KB1; kb++) {
        asm volatile("cp.async.wait_group 2;" ::: "memory");
        __syncthreads();
        const __half* st  = smh + (size_t)(kb % STG1) * ST1H;
        const __half* sA  = st;
        const __half* sB1 = st + TILE_H;
        const __half* sB3 = st + 2 * TILE_H;
#pragma unroll
        for (int ks = 0; ks < 2; ks++) {
            int kk = ks * 16 + 2 * q;
            uint32_t a[2][4];
#pragma unroll
            for (int i = 0; i < 2; i++) {
                int r = wm * 32 + i * 16 + grp;
                a[i][0] = *(const uint32_t*)(sA + r * AK + kk);
                a[i][1] = *(const uint32_t*)(sA + (r + 8) * AK + kk);
                a[i][2] = *(const uint32_t*)(sA + r * AK + kk + 8);
                a[i][3] = *(const uint32_t*)(sA + (r + 8) * AK + kk + 8);
            }
            uint32_t b1[4][2], b3[4][2];
#pragma unroll
            for (int j = 0; j < 4; j++) {
                int c = wn * 32 + j * 8 + grp;
                b1[j][0] = *(const uint32_t*)(sB1 + c * AK + kk);
                b1[j][1] = *(const uint32_t*)(sB1 + c * AK + kk + 8);
                b3[j][0] = *(const uint32_t*)(sB3 + c * AK + kk);
                b3[j][1] = *(const uint32_t*)(sB3 + c * AK + kk + 8);
            }
#pragma unroll
            for (int i = 0; i < 2; i++)
#pragma unroll
                for (int j = 0; j < 4; j++) {
                    mma16(accZ[i][j], a[i], b1[j]);
                    mma16(accG[i][j], a[i], b3[j]);
                }
        }
        if (kb + 3 < KB1) load_stage(kb + 3, (kb + 3) % STG1);
        else CP_COMMIT();
    }

    __half* gH = g_h + (size_t)ho * HID + n0;
#pragma unroll
    for (int i = 0; i < 2; i++) {
        int r = wm * 32 + i * 16 + grp;
#pragma unroll
        for (int j = 0; j < 4; j++) {
            int c = wn * 32 + j * 8 + 2 * q;
            float h[4];
#pragma unroll
            for (int t2 = 0; t2 < 4; t2++) {
                float z = accZ[i][j][t2];
                float g = accG[i][j][t2];
                h[t2] = (z / (1.f + __expf(-z))) * g;
            }
            __half2 lo = __floats2half2_rn(h[0], h[1]);
            __half2 hi = __floats2half2_rn(h[2], h[3]);
            *(uint32_t*)(gH + (size_t)r * HID + c)       = *(uint32_t*)&lo;
            *(uint32_t*)(gH + (size_t)(r + 8) * HID + c) = *(uint32_t*)&hi;
        }
    }
}

// ===================== GEMM2: out += gate * (H @ W2) =====================
#define ST2H  (2 * TILE_H)
#define STG2  5
#define KB2   (HID / 32)

__global__ void __launch_bounds__(512, 1) k_mma2(float* __restrict__ out) {
    extern __shared__ __half smh[];
    int e = blockIdx.z;
    int cnt = g_cnt[e];
    int m0 = blockIdx.y * 128;
    if (m0 >= cnt) return;
    int n0 = blockIdx.x * 128;
    int tid = threadIdx.x, lane = tid & 31, wid = tid >> 5;
    int wm = wid >> 2, wn = wid & 3;
    int grp = lane >> 2, q = lane & 3;
    uint32_t sbase = s2u(smh);
    int ho = offp_of(e) + m0;

    const __half* gA = g_h   + (size_t)ho * HID;
    const __half* gB = g_w2h + ((size_t)e * EMB + n0) * HID;

    auto load_stage = [&](int kb, int s) {
        uint32_t st = sbase + (uint32_t)s * ST2H * 2;
        int k0 = kb * 32;
        int r = tid >> 2, c = tid & 3;
        uint32_t so = (uint32_t)(r * AK) * 2 + c * 16;
        const size_t go = (size_t)r * HID + k0 + c * 8;
        cp16(st + so,              gA + go);
        cp16(st + TILE_H * 2 + so, gB + go);
        CP_COMMIT();
    };

    float acc[2][4][4];
#pragma unroll
    for (int i = 0; i < 2; i++)
#pragma unroll
        for (int j = 0; j < 4; j++)
#pragma unroll
            for (int r = 0; r < 4; r++) acc[i][j][r] = 0.f;

    load_stage(0, 0);
    load_stage(1, 1);
    load_stage(2, 2);
    load_stage(3, 3);

    for (int kb = 0; kb < KB2; kb++) {
        asm volatile("cp.async.wait_group 3;" ::: "memory");
        __syncthreads();
        const __half* st = smh + (size_t)(kb % STG2) * ST2H;
        const __half* sA = st;
        const __half* sB = st + TILE_H;
#pragma unroll
        for (int ks = 0; ks < 2; ks++) {
            int kk = ks * 16 + 2 * q;
            uint32_t a[2][4];
#pragma unroll
            for (int i = 0; i < 2; i++) {
                int r = wm * 32 + i * 16 + grp;
                a[i][0] = *(const uint32_t*)(sA + r * AK + kk);
                a[i][1] = *(const uint32_t*)(sA + (r + 8) * AK + kk);
                a[i][2] = *(const uint32_t*)(sA + r * AK + kk + 8);
                a[i][3] = *(const uint32_t*)(sA + (r + 8) * AK + kk + 8);
            }
            uint32_t b[4][2];
#pragma unroll
            for (int j = 0; j < 4; j++) {
                int c = wn * 32 + j * 8 + grp;
                b[j][0] = *(const uint32_t*)(sB + c * AK + kk);
                b[j][1] = *(const uint32_t*)(sB + c * AK + kk + 8);
            }
#pragma unroll
            for (int i = 0; i < 2; i++)
#pragma unroll
                for (int j = 0; j < 4; j++)
                    mma16(acc[i][j], a[i], b[j]);
        }
        if (kb + 4 < KB2) load_stage(kb + 4, (kb + 4) % STG2);
        else CP_COMMIT();
    }

#pragma unroll
    for (int i = 0; i < 2; i++) {
        int r = wm * 32 + i * 16 + grp;
        int row0 = m0 + r, row1 = row0 + 8;
        bool act0 = row0 < cnt, act1 = row1 < cnt;
        int   t0 = act0 ? g_tok[e][row0] : 0;
        int   t1 = act1 ? g_tok[e][row1] : 0;
        float gt0 = act0 ? g_gate[e][row0] : 0.f;
        float gt1 = act1 ? g_gate[e][row1] : 0.f;
        float* o0 = out + (size_t)t0 * EMB + n0;
        float* o1 = out + (size_t)t1 * EMB + n0;
#pragma unroll
        for (int j = 0; j < 4; j++) {
            int c = wn * 32 + j * 8 + 2 * q;
            if (act0) {
                atomicAdd(&o0[c],     gt0 * acc[i][j][0]);
                atomicAdd(&o0[c + 1], gt0 * acc[i][j][1]);
            }
            if (act1) {
                atomicAdd(&o1[c],     gt1 * acc[i][j][2]);
                atomicAdd(&o1[c + 1], gt1 * acc[i][j][3]);
            }
        }
    }
}

// ===================== launcher =====================
extern "C" void kernel_launch(void* const* d_in, const int* in_sizes, int n_in,
                              void* d_out, int out_size) {
    const float* x  = (const float*)d_in[0];
    const float* wr = (const float*)d_in[1];
    const float* w1 = (const float*)d_in[2];
    const float* w3 = (const float*)d_in[3];
    const float* w2 = (const float*)d_in[4];
    float* out = (float*)d_out;

    const int SM1 = STG1 * ST1H * 2;   // 122880
    const int SM2 = STG2 * ST2H * 2;   // 102400
    cudaFuncSetAttribute(k_mma1, cudaFuncAttributeMaxDynamicSharedMemorySize, SM1);
    cudaFuncSetAttribute(k_mma2, cudaFuncAttributeMaxDynamicSharedMemorySize, SM2);

    k_roundT<<<dim3(HID / 32, EMB / 32, 3 * NE), dim3(32, 8)>>>(w1, w3, w2);
    k_router<<<NTOK / 8, 256>>>(x, wr);
    k_gather<<<dim3(NTOK / 16, NE), 256>>>(x);

    k_mma1<<<dim3(HID / 128, NTOK / 128, NE), 512, SM1>>>();

    cudaMemsetAsync(out, 0, (size_t)out_size * sizeof(float));
    k_mma2<<<dim3(EMB / 128, NTOK / 128, NE), 512, SM2>>>(out);
}

// round 8
// speedup vs baseline: 1.6967x; 1.1050x over previous
#include <cuda_runtime.h>
#include <cuda_fp16.h>
#include <cstdint>
#include <math.h>

#define NTOK 4096
#define EMB  1024
#define HID  2816
#define NE   8
#define MAXPAD 9216

// ===================== device scratch =====================
__device__ int   g_cnt[NE];
__device__ int   g_tok[NE][NTOK];
__device__ float g_gate[NE][NTOK];

__device__ __half g_xp[(size_t)MAXPAD * EMB];
__device__ __half g_h [(size_t)MAXPAD * HID];
__device__ __half g_w1h[(size_t)NE * HID * EMB];   // [e][n][k]
__device__ __half g_w3h[(size_t)NE * HID * EMB];
__device__ __half g_w2h[(size_t)NE * EMB * HID];   // [e][n=EMB][k=HID]

// ===================== helpers =====================
__device__ __forceinline__ void mma16(float* c, const uint32_t* a, const uint32_t* b) {
    asm volatile("mma.sync.aligned.m16n8k16.row.col.f32.f16.f16.f32 "
        "{%0,%1,%2,%3}, {%4,%5,%6,%7}, {%8,%9}, {%0,%1,%2,%3};"
        : "+f"(c[0]), "+f"(c[1]), "+f"(c[2]), "+f"(c[3])
        : "r"(a[0]), "r"(a[1]), "r"(a[2]), "r"(a[3]), "r"(b[0]), "r"(b[1]));
}
__device__ __forceinline__ void ldsm4(uint32_t* r, uint32_t addr) {
    asm volatile("ldmatrix.sync.aligned.m8n8.x4.shared.b16 {%0,%1,%2,%3}, [%4];"
        : "=r"(r[0]), "=r"(r[1]), "=r"(r[2]), "=r"(r[3]) : "r"(addr));
}
__device__ __forceinline__ uint32_t s2u(const void* p) {
    uint32_t a;
    asm("{ .reg .u64 t; cvta.to.shared.u64 t, %1; cvt.u32.u64 %0, t; }" : "=r"(a) : "l"(p));
    return a;
}
__device__ __forceinline__ void cp16(uint32_t dst, const void* src) {
    asm volatile("cp.async.cg.shared.global [%0], [%1], 16;" :: "r"(dst), "l"(src));
}
#define CP_COMMIT() asm volatile("cp.async.commit_group;" ::: "memory")

__device__ __forceinline__ int offp_of(int e) {
    int o = 0;
    for (int i = 0; i < NE; i++) if (i < e) o += (g_cnt[i] + 127) & ~127;
    return o;
}

// ===== fused: fp16-convert + transpose weights to [e][n][k], reset cnt =====
__global__ void k_roundT(const float* __restrict__ w1,
                         const float* __restrict__ w3,
                         const float* __restrict__ w2) {
    __shared__ float t[32][33];
    int which = blockIdx.z / NE, e = blockIdx.z % NE;
    if (which == 0 && blockIdx.x == 0 && blockIdx.y == 0 &&
        threadIdx.y == 0 && threadIdx.x < NE) g_cnt[threadIdx.x] = 0;

    const float* in; __half* outp; int K, N, nt, kt;
    if (which < 2) {
        in = ((which == 0) ? w1 : w3) + (size_t)e * EMB * HID;
        outp = ((which == 0) ? g_w1h : g_w3h) + (size_t)e * HID * EMB;
        K = EMB; N = HID; nt = blockIdx.x; kt = blockIdx.y;
    } else {
        in = w2 + (size_t)e * HID * EMB;
        outp = g_w2h + (size_t)e * EMB * HID;
        K = HID; N = EMB; kt = blockIdx.x; nt = blockIdx.y;
    }
    int tx = threadIdx.x, ty = threadIdx.y;
#pragma unroll
    for (int i = 0; i < 4; i++)
        t[ty + 8 * i][tx] = in[(size_t)(kt * 32 + ty + 8 * i) * N + nt * 32 + tx];
    __syncthreads();
#pragma unroll
    for (int i = 0; i < 4; i++)
        outp[(size_t)(nt * 32 + ty + 8 * i) * K + kt * 32 + tx] =
            __float2half_rn(t[tx][ty + 8 * i]);
}

// ===================== router =====================
__global__ void k_router(const float* __restrict__ x, const float* __restrict__ wr) {
    int t    = blockIdx.x * (blockDim.x >> 5) + (threadIdx.x >> 5);
    int lane = threadIdx.x & 31;
    if (t >= NTOK) return;
    const float* xr = x + (size_t)t * EMB;
    float acc[NE];
#pragma unroll
    for (int e = 0; e < NE; e++) acc[e] = 0.f;
    for (int i = lane; i < EMB; i += 32) {
        float xv = xr[i];
#pragma unroll
        for (int e = 0; e < NE; e++) acc[e] += xv * wr[i * NE + e];
    }
#pragma unroll
    for (int e = 0; e < NE; e++)
#pragma unroll
        for (int o = 16; o > 0; o >>= 1) acc[e] += __shfl_xor_sync(0xffffffffu, acc[e], o);
    if (lane == 0) {
        int i0 = 0; float v0 = acc[0];
#pragma unroll
        for (int e = 1; e < NE; e++) if (acc[e] > v0) { v0 = acc[e]; i0 = e; }
        int i1 = -1; float v1 = -3.4e38f;
#pragma unroll
        for (int e = 0; e < NE; e++) if (e != i0 && acc[e] > v1) { v1 = acc[e]; i1 = e; }
        float z  = expf(v1 - v0);
        float p0 = 1.f / (1.f + z);
        float p1 = z  / (1.f + z);
        int s0 = atomicAdd(&g_cnt[i0], 1);
        g_tok[i0][s0] = t; g_gate[i0][s0] = p0;
        int s1 = atomicAdd(&g_cnt[i1], 1);
        g_tok[i1][s1] = t; g_gate[i1][s1] = p1;
    }
}

// ===================== gather -> fp16 ====================
__global__ void k_gather(const float* __restrict__ x) {
    int e = blockIdx.y; int cnt = g_cnt[e];
    int m0 = blockIdx.x * 16;
    int padded = (cnt + 127) & ~127;
    if (m0 >= padded) return;
    __half* dst = g_xp + (size_t)(offp_of(e) + m0) * EMB;
    for (int idx = threadIdx.x; idx < 16 * 128; idx += 256) {
        int r = idx >> 7, j = idx & 127;
        int gm = m0 + r;
        uint4 o = make_uint4(0, 0, 0, 0);
        if (gm < cnt) {
            const float4* src = (const float4*)(x + (size_t)g_tok[e][gm] * EMB) + j * 2;
            float4 v0 = src[0], v1 = src[1];
            __half2 h0 = __floats2half2_rn(v0.x, v0.y);
            __half2 h1 = __floats2half2_rn(v0.z, v0.w);
            __half2 h2 = __floats2half2_rn(v1.x, v1.y);
            __half2 h3 = __floats2half2_rn(v1.z, v1.w);
            o = make_uint4(*(uint32_t*)&h0, *(uint32_t*)&h1,
                           *(uint32_t*)&h2, *(uint32_t*)&h3);
        }
        ((uint4*)(dst + (size_t)r * EMB))[j] = o;
    }
}

// ===================== GEMM1: H = silu(X@W1)*(X@W3) =====================
// 128x128x32 CTA tile, 16 warps (4x4), warp tile 32x32, m16n8k16 + ldmatrix
#define AK    40
#define TILE_H (128 * AK)
#define ST1H  (3 * TILE_H)
#define STG1  4
#define KB1   (EMB / 32)

__global__ void __launch_bounds__(512, 1) k_mma1() {
    extern __shared__ __half smh[];
    int e = blockIdx.z;
    int cnt = g_cnt[e];
    int m0 = blockIdx.y * 128;
    if (m0 >= cnt) return;
    int n0 = blockIdx.x * 128;
    int tid = threadIdx.x, lane = tid & 31, wid = tid >> 5;
    int wm = wid >> 2, wn = wid & 3;
    int grp = lane >> 2, q = lane & 3;
    uint32_t sbase = s2u(smh);
    int ho = offp_of(e) + m0;

    // ldmatrix per-lane byte offsets (within a tile)
    uint32_t aoff[2], boff[2];
#pragma unroll
    for (int i = 0; i < 2; i++)
        aoff[i] = (uint32_t)(((wm * 32 + i * 16 + (lane & 15)) * AK + 8 * (lane >> 4)) * 2);
#pragma unroll
    for (int jp = 0; jp < 2; jp++)
        boff[jp] = (uint32_t)(((wn * 32 + jp * 16 + (lane & 7) + 8 * (lane >> 4)) * AK
                               + 8 * ((lane >> 3) & 1)) * 2);

    const __half* gA  = g_xp  + (size_t)ho * EMB;
    const __half* gB1 = g_w1h + ((size_t)e * HID + n0) * EMB;
    const __half* gB3 = g_w3h + ((size_t)e * HID + n0) * EMB;

    auto load_stage = [&](int kb, int s) {
        uint32_t st = sbase + (uint32_t)s * ST1H * 2;
        int k0 = kb * 32;
        int r = tid >> 2, c = tid & 3;
        uint32_t so = (uint32_t)(r * AK) * 2 + c * 16;
        const size_t go = (size_t)r * EMB + k0 + c * 8;
        cp16(st + so,              gA  + go);
        cp16(st + TILE_H * 2 + so, gB1 + go);
        cp16(st + TILE_H * 4 + so, gB3 + go);
        CP_COMMIT();
    };

    float accZ[2][4][4], accG[2][4][4];
#pragma unroll
    for (int i = 0; i < 2; i++)
#pragma unroll
        for (int j = 0; j < 4; j++)
#pragma unroll
            for (int r = 0; r < 4; r++) { accZ[i][j][r] = 0.f; accG[i][j][r] = 0.f; }

    load_stage(0, 0);
    load_stage(1, 1);
    load_stage(2, 2);

    for (int kb = 0; kb < KB1; kb++) {
        asm volatile("cp.async.wait_group 2;" ::: "memory");
        __syncthreads();
        uint32_t stA = sbase + (uint32_t)(kb % STG1) * ST1H * 2;
        uint32_t stB1 = stA + TILE_H * 2;
        uint32_t stB3 = stA + TILE_H * 4;
#pragma unroll
        for (int ks = 0; ks < 2; ks++) {
            uint32_t ko = ks * 32;                  // 16 halves
            uint32_t a[2][4], b1[2][4], b3[2][4];
#pragma unroll
            for (int i = 0; i < 2; i++)  ldsm4(a[i],  stA  + aoff[i] + ko);
#pragma unroll
            for (int jp = 0; jp < 2; jp++) {
                ldsm4(b1[jp], stB1 + boff[jp] + ko);
                ldsm4(b3[jp], stB3 + boff[jp] + ko);
            }
#pragma unroll
            for (int i = 0; i < 2; i++)
#pragma unroll
                for (int jp = 0; jp < 2; jp++) {
                    mma16(accZ[i][jp * 2],     a[i], b1[jp]);
                    mma16(accZ[i][jp * 2 + 1], a[i], b1[jp] + 2);
                    mma16(accG[i][jp * 2],     a[i], b3[jp]);
                    mma16(accG[i][jp * 2 + 1], a[i], b3[jp] + 2);
                }
        }
        if (kb + 3 < KB1) load_stage(kb + 3, (kb + 3) % STG1);
        else CP_COMMIT();
    }

    __half* gH = g_h + (size_t)ho * HID + n0;
#pragma unroll
    for (int i = 0; i < 2; i++) {
        int r = wm * 32 + i * 16 + grp;
#pragma unroll
        for (int j = 0; j < 4; j++) {
            int c = wn * 32 + j * 8 + 2 * q;
            float h[4];
#pragma unroll
            for (int t2 = 0; t2 < 4; t2++) {
                float z = accZ[i][j][t2];
                float g = accG[i][j][t2];
                h[t2] = (z / (1.f + __expf(-z))) * g;
            }
            __half2 lo = __floats2half2_rn(h[0], h[1]);
            __half2 hi = __floats2half2_rn(h[2], h[3]);
            *(uint32_t*)(gH + (size_t)r * HID + c)       = *(uint32_t*)&lo;
            *(uint32_t*)(gH + (size_t)(r + 8) * HID + c) = *(uint32_t*)&hi;
        }
    }
}

// ===================== GEMM2: out += gate * (H @ W2) =====================
#define ST2H  (2 * TILE_H)
#define STG2  5
#define KB2   (HID / 32)

__global__ void __launch_bounds__(512, 1) k_mma2(float* __restrict__ out) {
    extern __shared__ __half smh[];
    int e = blockIdx.z;
    int cnt = g_cnt[e];
    int m0 = blockIdx.y * 128;
    if (m0 >= cnt) return;
    int n0 = blockIdx.x * 128;
    int tid = threadIdx.x, lane = tid & 31, wid = tid >> 5;
    int wm = wid >> 2, wn = wid & 3;
    int grp = lane >> 2, q = lane & 3;
    uint32_t sbase = s2u(smh);
    int ho = offp_of(e) + m0;

    uint32_t aoff[2], boff[2];
#pragma unroll
    for (int i = 0; i < 2; i++)
        aoff[i] = (uint32_t)(((wm * 32 + i * 16 + (lane & 15)) * AK + 8 * (lane >> 4)) * 2);
#pragma unroll
    for (int jp = 0; jp < 2; jp++)
        boff[jp] = (uint32_t)(((wn * 32 + jp * 16 + (lane & 7) + 8 * (lane >> 4)) * AK
                               + 8 * ((lane >> 3) & 1)) * 2);

    const __half* gA = g_h   + (size_t)ho * HID;
    const __half* gB = g_w2h + ((size_t)e * EMB + n0) * HID;

    auto load_stage = [&](int kb, int s) {
        uint32_t st = sbase + (uint32_t)s * ST2H * 2;
        int k0 = kb * 32;
        int r = tid >> 2, c = tid & 3;
        uint32_t so = (uint32_t)(r * AK) * 2 + c * 16;
        const size_t go = (size_t)r * HID + k0 + c * 8;
        cp16(st + so,              gA + go);
        cp16(st + TILE_H * 2 + so, gB + go);
        CP_COMMIT();
    };

    float acc[2][4][4];
#pragma unroll
    for (int i = 0; i < 2; i++)
#pragma unroll
        for (int j = 0; j < 4; j++)
#pragma unroll
            for (int r = 0; r < 4; r++) acc[i][j][r] = 0.f;

    load_stage(0, 0);
    load_stage(1, 1);
    load_stage(2, 2);
    load_stage(3, 3);

    for (int kb = 0; kb < KB2; kb++) {
        asm volatile("cp.async.wait_group 3;" ::: "memory");
        __syncthreads();
        uint32_t stA = sbase + (uint32_t)(kb % STG2) * ST2H * 2;
        uint32_t stB = stA + TILE_H * 2;
#pragma unroll
        for (int ks = 0; ks < 2; ks++) {
            uint32_t ko = ks * 32;
            uint32_t a[2][4], b[2][4];
#pragma unroll
            for (int i = 0; i < 2; i++)  ldsm4(a[i], stA + aoff[i] + ko);
#pragma unroll
            for (int jp = 0; jp < 2; jp++) ldsm4(b[jp], stB + boff[jp] + ko);
#pragma unroll
            for (int i = 0; i < 2; i++)
#pragma unroll
                for (int jp = 0; jp < 2; jp++) {
                    mma16(acc[i][jp * 2],     a[i], b[jp]);
                    mma16(acc[i][jp * 2 + 1], a[i], b[jp] + 2);
                }
        }
        if (kb + 4 < KB2) load_stage(kb + 4, (kb + 4) % STG2);
        else CP_COMMIT();
    }

#pragma unroll
    for (int i = 0; i < 2; i++) {
        int r = wm * 32 + i * 16 + grp;
        int row0 = m0 + r, row1 = row0 + 8;
        bool act0 = row0 < cnt, act1 = row1 < cnt;
        int   t0 = act0 ? g_tok[e][row0] : 0;
        int   t1 = act1 ? g_tok[e][row1] : 0;
        float gt0 = act0 ? g_gate[e][row0] : 0.f;
        float gt1 = act1 ? g_gate[e][row1] : 0.f;
        float* o0 = out + (size_t)t0 * EMB + n0;
        float* o1 = out + (size_t)t1 * EMB + n0;
#pragma unroll
        for (int j = 0; j < 4; j++) {
            int c = wn * 32 + j * 8 + 2 * q;
            if (act0) {
                atomicAdd(&o0[c],     gt0 * acc[i][j][0]);
                atomicAdd(&o0[c + 1], gt0 * acc[i][j][1]);
            }
            if (act1) {
                atomicAdd(&o1[c],     gt1 * acc[i][j][2]);
                atomicAdd(&o1[c + 1], gt1 * acc[i][j][3]);
            }
        }
    }
}

// ===================== launcher =====================
extern "C" void kernel_launch(void* const* d_in, const int* in_sizes, int n_in,
                              void* d_out, int out_size) {
    const float* x  = (const float*)d_in[0];
    const float* wr = (const float*)d_in[1];
    const float* w1 = (const float*)d_in[2];
    const float* w3 = (const float*)d_in[3];
    const float* w2 = (const float*)d_in[4];
    float* out = (float*)d_out;

    const int SM1 = STG1 * ST1H * 2;   // 122880
    const int SM2 = STG2 * ST2H * 2;   // 102400
    cudaFuncSetAttribute(k_mma1, cudaFuncAttributeMaxDynamicSharedMemorySize, SM1);
    cudaFuncSetAttribute(k_mma2, cudaFuncAttributeMaxDynamicSharedMemorySize, SM2);

    k_roundT<<<dim3(HID / 32, EMB / 32, 3 * NE), dim3(32, 8)>>>(w1, w3, w2);
    k_router<<<NTOK / 8, 256>>>(x, wr);
    k_gather<<<dim3(NTOK / 16, NE), 256>>>(x);

    k_mma1<<<dim3(HID / 128, NTOK / 128, NE), 512, SM1>>>();

    cudaMemsetAsync(out, 0, (size_t)out_size * sizeof(float));
    k_mma2<<<dim3(EMB / 128, NTOK / 128, NE), 512, SM2>>>(out);
}

// round 9
// speedup vs baseline: 1.7074x; 1.0063x over previous
#include <cuda_runtime.h>
#include <cuda_fp16.h>
#include <cstdint>
#include <math.h>

#define NTOK 4096
#define EMB  1024
#define HID  2816
#define NE   8
#define MAXPAD 9216

// ===================== device scratch =====================
__device__ int   g_cnt[NE];
__device__ int   g_tok[NE][NTOK];
__device__ float g_gate[NE][NTOK];

__device__ __half g_xp[(size_t)MAXPAD * EMB];
__device__ __half g_h [(size_t)MAXPAD * HID];
__device__ __half g_w1h[(size_t)NE * HID * EMB];   // [e][n][k]
__device__ __half g_w3h[(size_t)NE * HID * EMB];
__device__ __half g_w2h[(size_t)NE * EMB * HID];   // [e][n=EMB][k=HID]

// ===================== helpers =====================
__device__ __forceinline__ void mma16(float* c, const uint32_t* a, const uint32_t* b) {
    asm volatile("mma.sync.aligned.m16n8k16.row.col.f32.f16.f16.f32 "
        "{%0,%1,%2,%3}, {%4,%5,%6,%7}, {%8,%9}, {%0,%1,%2,%3};"
        : "+f"(c[0]), "+f"(c[1]), "+f"(c[2]), "+f"(c[3])
        : "r"(a[0]), "r"(a[1]), "r"(a[2]), "r"(a[3]), "r"(b[0]), "r"(b[1]));
}
__device__ __forceinline__ void ldsm4(uint32_t* r, uint32_t addr) {
    asm volatile("ldmatrix.sync.aligned.m8n8.x4.shared.b16 {%0,%1,%2,%3}, [%4];"
        : "=r"(r[0]), "=r"(r[1]), "=r"(r[2]), "=r"(r[3]) : "r"(addr));
}
__device__ __forceinline__ uint32_t s2u(const void* p) {
    uint32_t a;
    asm("{ .reg .u64 t; cvta.to.shared.u64 t, %1; cvt.u32.u64 %0, t; }" : "=r"(a) : "l"(p));
    return a;
}
__device__ __forceinline__ void cp16(uint32_t dst, const void* src) {
    asm volatile("cp.async.cg.shared.global [%0], [%1], 16;" :: "r"(dst), "l"(src));
}
#define CP_COMMIT() asm volatile("cp.async.commit_group;" ::: "memory")

__device__ __forceinline__ int offp_of(int e) {
    int o = 0;
    for (int i = 0; i < NE; i++) if (i < e) o += (g_cnt[i] + 127) & ~127;
    return o;
}

// ===== fused: fp16-convert + transpose weights to [e][n][k], reset cnt =====
__global__ void k_roundT(const float* __restrict__ w1,
                         const float* __restrict__ w3,
                         const float* __restrict__ w2) {
    __shared__ float t[32][33];
    int which = blockIdx.z / NE, e = blockIdx.z % NE;
    if (which == 0 && blockIdx.x == 0 && blockIdx.y == 0 &&
        threadIdx.y == 0 && threadIdx.x < NE) g_cnt[threadIdx.x] = 0;

    const float* in; __half* outp; int K, N, nt, kt;
    if (which < 2) {
        in = ((which == 0) ? w1 : w3) + (size_t)e * EMB * HID;
        outp = ((which == 0) ? g_w1h : g_w3h) + (size_t)e * HID * EMB;
        K = EMB; N = HID; nt = blockIdx.x; kt = blockIdx.y;
    } else {
        in = w2 + (size_t)e * HID * EMB;
        outp = g_w2h + (size_t)e * EMB * HID;
        K = HID; N = EMB; kt = blockIdx.x; nt = blockIdx.y;
    }
    int tx = threadIdx.x, ty = threadIdx.y;
#pragma unroll
    for (int i = 0; i < 4; i++)
        t[ty + 8 * i][tx] = in[(size_t)(kt * 32 + ty + 8 * i) * N + nt * 32 + tx];
    __syncthreads();
#pragma unroll
    for (int i = 0; i < 4; i++)
        outp[(size_t)(nt * 32 + ty + 8 * i) * K + kt * 32 + tx] =
            __float2half_rn(t[tx][ty + 8 * i]);
}

// ===================== router =====================
__global__ void k_router(const float* __restrict__ x, const float* __restrict__ wr) {
    int t    = blockIdx.x * (blockDim.x >> 5) + (threadIdx.x >> 5);
    int lane = threadIdx.x & 31;
    if (t >= NTOK) return;
    const float* xr = x + (size_t)t * EMB;
    float acc[NE];
#pragma unroll
    for (int e = 0; e < NE; e++) acc[e] = 0.f;
    for (int i = lane; i < EMB; i += 32) {
        float xv = xr[i];
#pragma unroll
        for (int e = 0; e < NE; e++) acc[e] += xv * wr[i * NE + e];
    }
#pragma unroll
    for (int e = 0; e < NE; e++)
#pragma unroll
        for (int o = 16; o > 0; o >>= 1) acc[e] += __shfl_xor_sync(0xffffffffu, acc[e], o);
    if (lane == 0) {
        int i0 = 0; float v0 = acc[0];
#pragma unroll
        for (int e = 1; e < NE; e++) if (acc[e] > v0) { v0 = acc[e]; i0 = e; }
        int i1 = -1; float v1 = -3.4e38f;
#pragma unroll
        for (int e = 0; e < NE; e++) if (e != i0 && acc[e] > v1) { v1 = acc[e]; i1 = e; }
        float z  = expf(v1 - v0);
        float p0 = 1.f / (1.f + z);
        float p1 = z  / (1.f + z);
        int s0 = atomicAdd(&g_cnt[i0], 1);
        g_tok[i0][s0] = t; g_gate[i0][s0] = p0;
        int s1 = atomicAdd(&g_cnt[i1], 1);
        g_tok[i1][s1] = t; g_gate[i1][s1] = p1;
    }
}

// ===================== gather -> fp16 ====================
__global__ void k_gather(const float* __restrict__ x) {
    int e = blockIdx.y; int cnt = g_cnt[e];
    int m0 = blockIdx.x * 16;
    int padded = (cnt + 127) & ~127;
    if (m0 >= padded) return;
    __half* dst = g_xp + (size_t)(offp_of(e) + m0) * EMB;
    for (int idx = threadIdx.x; idx < 16 * 128; idx += 256) {
        int r = idx >> 7, j = idx & 127;
        int gm = m0 + r;
        uint4 o = make_uint4(0, 0, 0, 0);
        if (gm < cnt) {
            const float4* src = (const float4*)(x + (size_t)g_tok[e][gm] * EMB) + j * 2;
            float4 v0 = src[0], v1 = src[1];
            __half2 h0 = __floats2half2_rn(v0.x, v0.y);
            __half2 h1 = __floats2half2_rn(v0.z, v0.w);
            __half2 h2 = __floats2half2_rn(v1.x, v1.y);
            __half2 h3 = __floats2half2_rn(v1.z, v1.w);
            o = make_uint4(*(uint32_t*)&h0, *(uint32_t*)&h1,
                           *(uint32_t*)&h2, *(uint32_t*)&h3);
        }
        ((uint4*)(dst + (size_t)r * EMB))[j] = o;
    }
}

// ===================== GEMM1: H = silu(X@W1)*(X@W3) =====================
// CTA tile 128(M)x64(N)x32(K), 8 warps (4x2), warp tile 32x32, 2 CTAs/SM
#define AK    40
#define A_T_H (128 * AK)       // 5120 halves
#define B_T_H (64 * AK)        // 2560 halves
#define ST1H  (A_T_H + 2 * B_T_H)   // 10240 halves = 20480 B
#define STG1  5
#define KB1   (EMB / 32)

__global__ void __launch_bounds__(256, 2) k_mma1() {
    extern __shared__ __half smh[];
    int e = blockIdx.z;
    int cnt = g_cnt[e];
    int m0 = blockIdx.y * 128;
    if (m0 >= cnt) return;
    int n0 = blockIdx.x * 64;
    int tid = threadIdx.x, lane = tid & 31, wid = tid >> 5;
    int wm = wid >> 1, wn = wid & 1;     // 4 x 2
    int grp = lane >> 2, q = lane & 3;
    uint32_t sbase = s2u(smh);
    int ho = offp_of(e) + m0;

    uint32_t aoff[2], boff[2];
#pragma unroll
    for (int i = 0; i < 2; i++)
        aoff[i] = (uint32_t)(((wm * 32 + i * 16 + (lane & 15)) * AK + 8 * (lane >> 4)) * 2);
#pragma unroll
    for (int jp = 0; jp < 2; jp++)
        boff[jp] = (uint32_t)(((wn * 32 + jp * 16 + (lane & 7) + 8 * (lane >> 4)) * AK
                               + 8 * ((lane >> 3) & 1)) * 2);

    const __half* gA  = g_xp  + (size_t)ho * EMB;
    const __half* gB1 = g_w1h + ((size_t)e * HID + n0) * EMB;
    const __half* gB3 = g_w3h + ((size_t)e * HID + n0) * EMB;

    auto load_stage = [&](int kb, int s) {
        uint32_t st = sbase + (uint32_t)s * ST1H * 2;
        int k0 = kb * 32;
#pragma unroll
        for (int it = 0; it < 2; it++) {          // A: 128 rows
            int id = it * 256 + tid;
            int r = id >> 2, c = id & 3;
            cp16(st + (uint32_t)(r * AK) * 2 + c * 16, gA + (size_t)r * EMB + k0 + c * 8);
        }
        {                                          // B1/B3: 64 rows each
            int r = tid >> 2, c = tid & 3;
            uint32_t so = (uint32_t)(r * AK) * 2 + c * 16;
            const size_t go = (size_t)r * EMB + k0 + c * 8;
            cp16(st + A_T_H * 2 + so,               gB1 + go);
            cp16(st + (A_T_H + B_T_H) * 2 + so,     gB3 + go);
        }
        CP_COMMIT();
    };

    float accZ[2][4][4], accG[2][4][4];
#pragma unroll
    for (int i = 0; i < 2; i++)
#pragma unroll
        for (int j = 0; j < 4; j++)
#pragma unroll
            for (int r = 0; r < 4; r++) { accZ[i][j][r] = 0.f; accG[i][j][r] = 0.f; }

#pragma unroll
    for (int p = 0; p < STG1 - 1; p++) load_stage(p, p);

    for (int kb = 0; kb < KB1; kb++) {
        asm volatile("cp.async.wait_group %0;" :: "n"(STG1 - 2) : "memory");
        __syncthreads();
        uint32_t stA = sbase + (uint32_t)(kb % STG1) * ST1H * 2;
        uint32_t stB1 = stA + A_T_H * 2;
        uint32_t stB3 = stA + (A_T_H + B_T_H) * 2;
#pragma unroll
        for (int ks = 0; ks < 2; ks++) {
            uint32_t ko = ks * 32;
            uint32_t a[2][4], b1[4], b3[4];
#pragma unroll
            for (int i = 0; i < 2; i++) ldsm4(a[i], stA + aoff[i] + ko);
            ldsm4(b1, stB1 + boff[0] + ko);
            ldsm4(b3, stB3 + boff[0] + ko);
#pragma unroll
            for (int i = 0; i < 2; i++) {
                mma16(accZ[i][0], a[i], b1);
                mma16(accZ[i][1], a[i], b1 + 2);
                mma16(accG[i][0], a[i], b3);
                mma16(accG[i][1], a[i], b3 + 2);
            }
            ldsm4(b1, stB1 + boff[1] + ko);
            ldsm4(b3, stB3 + boff[1] + ko);
#pragma unroll
            for (int i = 0; i < 2; i++) {
                mma16(accZ[i][2], a[i], b1);
                mma16(accZ[i][3], a[i], b1 + 2);
                mma16(accG[i][2], a[i], b3);
                mma16(accG[i][3], a[i], b3 + 2);
            }
        }
        if (kb + STG1 - 1 < KB1) load_stage(kb + STG1 - 1, (kb + STG1 - 1) % STG1);
        else CP_COMMIT();
    }

    __half* gH = g_h + (size_t)ho * HID + n0;
#pragma unroll
    for (int i = 0; i < 2; i++) {
        int r = wm * 32 + i * 16 + grp;
#pragma unroll
        for (int j = 0; j < 4; j++) {
            int c = wn * 32 + j * 8 + 2 * q;
            float h[4];
#pragma unroll
            for (int t2 = 0; t2 < 4; t2++) {
                float z = accZ[i][j][t2];
                float g = accG[i][j][t2];
                h[t2] = (z / (1.f + __expf(-z))) * g;
            }
            __half2 lo = __floats2half2_rn(h[0], h[1]);
            __half2 hi = __floats2half2_rn(h[2], h[3]);
            *(uint32_t*)(gH + (size_t)r * HID + c)       = *(uint32_t*)&lo;
            *(uint32_t*)(gH + (size_t)(r + 8) * HID + c) = *(uint32_t*)&hi;
        }
    }
}

// ===================== GEMM2: out += gate * (H @ W2) =====================
#define ST2H  (A_T_H + B_T_H)   // 7680 halves = 15360 B
#define STG2  6
#define KB2   (HID / 32)

__global__ void __launch_bounds__(256, 2) k_mma2(float* __restrict__ out) {
    extern __shared__ __half smh[];
    int e = blockIdx.z;
    int cnt = g_cnt[e];
    int m0 = blockIdx.y * 128;
    if (m0 >= cnt) return;
    int n0 = blockIdx.x * 64;
    int tid = threadIdx.x, lane = tid & 31, wid = tid >> 5;
    int wm = wid >> 1, wn = wid & 1;
    int grp = lane >> 2, q = lane & 3;
    uint32_t sbase = s2u(smh);
    int ho = offp_of(e) + m0;

    uint32_t aoff[2], boff[2];
#pragma unroll
    for (int i = 0; i < 2; i++)
        aoff[i] = (uint32_t)(((wm * 32 + i * 16 + (lane & 15)) * AK + 8 * (lane >> 4)) * 2);
#pragma unroll
    for (int jp = 0; jp < 2; jp++)
        boff[jp] = (uint32_t)(((wn * 32 + jp * 16 + (lane & 7) + 8 * (lane >> 4)) * AK
                               + 8 * ((lane >> 3) & 1)) * 2);

    const __half* gA = g_h   + (size_t)ho * HID;
    const __half* gB = g_w2h + ((size_t)e * EMB + n0) * HID;

    auto load_stage = [&](int kb, int s) {
        uint32_t st = sbase + (uint32_t)s * ST2H * 2;
        int k0 = kb * 32;
#pragma unroll
        for (int it = 0; it < 2; it++) {
            int id = it * 256 + tid;
            int r = id >> 2, c = id & 3;
            cp16(st + (uint32_t)(r * AK) * 2 + c * 16, gA + (size_t)r * HID + k0 + c * 8);
        }
        {
            int r = tid >> 2, c = tid & 3;
            cp16(st + A_T_H * 2 + (uint32_t)(r * AK) * 2 + c * 16,
                 gB + (size_t)r * HID + k0 + c * 8);
        }
        CP_COMMIT();
    };

    float acc[2][4][4];
#pragma unroll
    for (int i = 0; i < 2; i++)
#pragma unroll
        for (int j = 0; j < 4; j++)
#pragma unroll
            for (int r = 0; r < 4; r++) acc[i][j][r] = 0.f;

#pragma unroll
    for (int p = 0; p < STG2 - 1; p++) load_stage(p, p);

    for (int kb = 0; kb < KB2; kb++) {
        asm volatile("cp.async.wait_group %0;" :: "n"(STG2 - 2) : "memory");
        __syncthreads();
        uint32_t stA = sbase + (uint32_t)(kb % STG2) * ST2H * 2;
        uint32_t stB = stA + A_T_H * 2;
#pragma unroll
        for (int ks = 0; ks < 2; ks++) {
            uint32_t ko = ks * 32;
            uint32_t a[2][4], b[2][4];
#pragma unroll
            for (int i = 0; i < 2; i++)  ldsm4(a[i], stA + aoff[i] + ko);
#pragma unroll
            for (int jp = 0; jp < 2; jp++) ldsm4(b[jp], stB + boff[jp] + ko);
#pragma unroll
            for (int i = 0; i < 2; i++)
#pragma unroll
                for (int jp = 0; jp < 2; jp++) {
                    mma16(acc[i][jp * 2],     a[i], b[jp]);
                    mma16(acc[i][jp * 2 + 1], a[i], b[jp] + 2);
                }
        }
        if (kb + STG2 - 1 < KB2) load_stage(kb + STG2 - 1, (kb + STG2 - 1) % STG2);
        else CP_COMMIT();
    }

#pragma unroll
    for (int i = 0; i < 2; i++) {
        int r = wm * 32 + i * 16 + grp;
        int row0 = m0 + r, row1 = row0 + 8;
        bool act0 = row0 < cnt, act1 = row1 < cnt;
        int   t0 = act0 ? g_tok[e][row0] : 0;
        int   t1 = act1 ? g_tok[e][row1] : 0;
        float gt0 = act0 ? g_gate[e][row0] : 0.f;
        float gt1 = act1 ? g_gate[e][row1] : 0.f;
        float* o0 = out + (size_t)t0 * EMB + n0;
        float* o1 = out + (size_t)t1 * EMB + n0;
#pragma unroll
        for (int j = 0; j < 4; j++) {
            int c = wn * 32 + j * 8 + 2 * q;
            if (act0) {
                atomicAdd(&o0[c],     gt0 * acc[i][j][0]);
                atomicAdd(&o0[c + 1], gt0 * acc[i][j][1]);
            }
            if (act1) {
                atomicAdd(&o1[c],     gt1 * acc[i][j][2]);
                atomicAdd(&o1[c + 1], gt1 * acc[i][j][3]);
            }
        }
    }
}

// ===================== launcher =====================
extern "C" void kernel_launch(void* const* d_in, const int* in_sizes, int n_in,
                              void* d_out, int out_size) {
    const float* x  = (const float*)d_in[0];
    const float* wr = (const float*)d_in[1];
    const float* w1 = (const float*)d_in[2];
    const float* w3 = (const float*)d_in[3];
    const float* w2 = (const float*)d_in[4];
    float* out = (float*)d_out;

    const int SM1 = STG1 * ST1H * 2;   // 102400
    const int SM2 = STG2 * ST2H * 2;   // 92160
    cudaFuncSetAttribute(k_mma1, cudaFuncAttributeMaxDynamicSharedMemorySize, SM1);
    cudaFuncSetAttribute(k_mma2, cudaFuncAttributeMaxDynamicSharedMemorySize, SM2);

    k_roundT<<<dim3(HID / 32, EMB / 32, 3 * NE), dim3(32, 8)>>>(w1, w3, w2);
    k_router<<<NTOK / 8, 256>>>(x, wr);
    k_gather<<<dim3(NTOK / 16, NE), 256>>>(x);

    k_mma1<<<dim3(HID / 64, NTOK / 128, NE), 256, SM1>>>();

    cudaMemsetAsync(out, 0, (size_t)out_size * sizeof(float));
    k_mma2<<<dim3(EMB / 64, NTOK / 128, NE), 256, SM2>>>(out);
}

// round 10
// speedup vs baseline: 1.9323x; 1.1317x over previous
#include <cuda_runtime.h>
#include <cuda_fp16.h>
#include <cstdint>
#include <math.h>

#define NTOK 4096
#define EMB  1024
#define HID  2816
#define NE   8
#define MAXPAD 9216

// ===================== device scratch =====================
__device__ int   g_cnt[NE];
__device__ int   g_tok[NE][NTOK];
__device__ float g_gate[NE][NTOK];

__device__ __half g_xp[(size_t)MAXPAD * EMB];
__device__ __half g_h [(size_t)MAXPAD * HID];
__device__ __half g_w1h[(size_t)NE * HID * EMB];   // [e][n][k]
__device__ __half g_w3h[(size_t)NE * HID * EMB];
__device__ __half g_w2h[(size_t)NE * EMB * HID];   // [e][n=EMB][k=HID]

// ===================== helpers =====================
__device__ __forceinline__ void mma16(float* c, const uint32_t* a, const uint32_t* b) {
    asm volatile("mma.sync.aligned.m16n8k16.row.col.f32.f16.f16.f32 "
        "{%0,%1,%2,%3}, {%4,%5,%6,%7}, {%8,%9}, {%0,%1,%2,%3};"
        : "+f"(c[0]), "+f"(c[1]), "+f"(c[2]), "+f"(c[3])
        : "r"(a[0]), "r"(a[1]), "r"(a[2]), "r"(a[3]), "r"(b[0]), "r"(b[1]));
}
__device__ __forceinline__ void ldsm4(uint32_t* r, uint32_t addr) {
    asm volatile("ldmatrix.sync.aligned.m8n8.x4.shared.b16 {%0,%1,%2,%3}, [%4];"
        : "=r"(r[0]), "=r"(r[1]), "=r"(r[2]), "=r"(r[3]) : "r"(addr));
}
__device__ __forceinline__ uint32_t s2u(const void* p) {
    uint32_t a;
    asm("{ .reg .u64 t; cvta.to.shared.u64 t, %1; cvt.u32.u64 %0, t; }" : "=r"(a) : "l"(p));
    return a;
}
__device__ __forceinline__ void cp16(uint32_t dst, const void* src) {
    asm volatile("cp.async.cg.shared.global [%0], [%1], 16;" :: "r"(dst), "l"(src));
}
#define CP_COMMIT() asm volatile("cp.async.commit_group;" ::: "memory")

__device__ __forceinline__ int offp_of(int e) {
    int o = 0;
    for (int i = 0; i < NE; i++) if (i < e) o += (g_cnt[i] + 127) & ~127;
    return o;
}

// ===== fused: fp16-convert + transpose weights to [e][n][k], reset cnt =====
__global__ void k_roundT(const float* __restrict__ w1,
                         const float* __restrict__ w3,
                         const float* __restrict__ w2) {
    __shared__ float t[32][33];
    int which = blockIdx.z / NE, e = blockIdx.z % NE;
    if (which == 0 && blockIdx.x == 0 && blockIdx.y == 0 &&
        threadIdx.y == 0 && threadIdx.x < NE) g_cnt[threadIdx.x] = 0;

    const float* in; __half* outp; int K, N, nt, kt;
    if (which < 2) {
        in = ((which == 0) ? w1 : w3) + (size_t)e * EMB * HID;
        outp = ((which == 0) ? g_w1h : g_w3h) + (size_t)e * HID * EMB;
        K = EMB; N = HID; nt = blockIdx.x; kt = blockIdx.y;
    } else {
        in = w2 + (size_t)e * HID * EMB;
        outp = g_w2h + (size_t)e * EMB * HID;
        K = HID; N = EMB; kt = blockIdx.x; nt = blockIdx.y;
    }
    int tx = threadIdx.x, ty = threadIdx.y;
#pragma unroll
    for (int i = 0; i < 4; i++)
        t[ty + 8 * i][tx] = in[(size_t)(kt * 32 + ty + 8 * i) * N + nt * 32 + tx];
    __syncthreads();
#pragma unroll
    for (int i = 0; i < 4; i++)
        outp[(size_t)(nt * 32 + ty + 8 * i) * K + kt * 32 + tx] =
            __float2half_rn(t[tx][ty + 8 * i]);
}

// ===================== router =====================
__global__ void k_router(const float* __restrict__ x, const float* __restrict__ wr) {
    int t    = blockIdx.x * (blockDim.x >> 5) + (threadIdx.x >> 5);
    int lane = threadIdx.x & 31;
    if (t >= NTOK) return;
    const float* xr = x + (size_t)t * EMB;
    float acc[NE];
#pragma unroll
    for (int e = 0; e < NE; e++) acc[e] = 0.f;
    for (int i = lane; i < EMB; i += 32) {
        float xv = xr[i];
#pragma unroll
        for (int e = 0; e < NE; e++) acc[e] += xv * wr[i * NE + e];
    }
#pragma unroll
    for (int e = 0; e < NE; e++)
#pragma unroll
        for (int o = 16; o > 0; o >>= 1) acc[e] += __shfl_xor_sync(0xffffffffu, acc[e], o);
    if (lane == 0) {
        int i0 = 0; float v0 = acc[0];
#pragma unroll
        for (int e = 1; e < NE; e++) if (acc[e] > v0) { v0 = acc[e]; i0 = e; }
        int i1 = -1; float v1 = -3.4e38f;
#pragma unroll
        for (int e = 0; e < NE; e++) if (e != i0 && acc[e] > v1) { v1 = acc[e]; i1 = e; }
        float z  = expf(v1 - v0);
        float p0 = 1.f / (1.f + z);
        float p1 = z  / (1.f + z);
        int s0 = atomicAdd(&g_cnt[i0], 1);
        g_tok[i0][s0] = t; g_gate[i0][s0] = p0;
        int s1 = atomicAdd(&g_cnt[i1], 1);
        g_tok[i1][s1] = t; g_gate[i1][s1] = p1;
    }
}

// ===================== gather -> fp16 ====================
__global__ void k_gather(const float* __restrict__ x) {
    int e = blockIdx.y; int cnt = g_cnt[e];
    int m0 = blockIdx.x * 16;
    int padded = (cnt + 127) & ~127;
    if (m0 >= padded) return;
    __half* dst = g_xp + (size_t)(offp_of(e) + m0) * EMB;
    for (int idx = threadIdx.x; idx < 16 * 128; idx += 256) {
        int r = idx >> 7, j = idx & 127;
        int gm = m0 + r;
        uint4 o = make_uint4(0, 0, 0, 0);
        if (gm < cnt) {
            const float4* src = (const float4*)(x + (size_t)g_tok[e][gm] * EMB) + j * 2;
            float4 v0 = src[0], v1 = src[1];
            __half2 h0 = __floats2half2_rn(v0.x, v0.y);
            __half2 h1 = __floats2half2_rn(v0.z, v0.w);
            __half2 h2 = __floats2half2_rn(v1.x, v1.y);
            __half2 h3 = __floats2half2_rn(v1.z, v1.w);
            o = make_uint4(*(uint32_t*)&h0, *(uint32_t*)&h1,
                           *(uint32_t*)&h2, *(uint32_t*)&h3);
        }
        ((uint4*)(dst + (size_t)r * EMB))[j] = o;
    }
}

// ===================== GEMM1: H = silu(X@W1)*(X@W3) =====================
// CTA tile 128(M)x64(N)x64(K), 8 warps (4x2), warp tile 32x32, 2 CTAs/SM
#define AK    72                    // 64 + 8 pad halves
#define A_T_H (128 * AK)            // 9216 halves = 18432 B
#define B_T_H (64 * AK)             // 4608 halves = 9216 B
#define ST1H  (A_T_H + 2 * B_T_H)   // 18432 halves = 36864 B
#define STG1  3
#define KB1   (EMB / 64)            // 16

__global__ void __launch_bounds__(256, 2) k_mma1() {
    extern __shared__ __half smh[];
    int e = blockIdx.z;
    int cnt = g_cnt[e];
    int m0 = blockIdx.y * 128;
    if (m0 >= cnt) return;
    int n0 = blockIdx.x * 64;
    int tid = threadIdx.x, lane = tid & 31, wid = tid >> 5;
    int wm = wid >> 1, wn = wid & 1;
    int grp = lane >> 2, q = lane & 3;
    uint32_t sbase = s2u(smh);
    int ho = offp_of(e) + m0;

    uint32_t aoff[2], boff[2];
#pragma unroll
    for (int i = 0; i < 2; i++)
        aoff[i] = (uint32_t)(((wm * 32 + i * 16 + (lane & 15)) * AK + 8 * (lane >> 4)) * 2);
#pragma unroll
    for (int jp = 0; jp < 2; jp++)
        boff[jp] = (uint32_t)(((wn * 32 + jp * 16 + (lane & 7) + 8 * (lane >> 4)) * AK
                               + 8 * ((lane >> 3) & 1)) * 2);

    const __half* gA  = g_xp  + (size_t)ho * EMB;
    const __half* gB1 = g_w1h + ((size_t)e * HID + n0) * EMB;
    const __half* gB3 = g_w3h + ((size_t)e * HID + n0) * EMB;

    auto load_stage = [&](int kb, int s) {
        uint32_t st = sbase + (uint32_t)s * ST1H * 2;
        int k0 = kb * 64;
#pragma unroll
        for (int it = 0; it < 4; it++) {          // A: 128 rows x 64 halves
            int id = it * 256 + tid;
            int r = id >> 3, c = id & 7;
            cp16(st + (uint32_t)(r * AK) * 2 + c * 16, gA + (size_t)r * EMB + k0 + c * 8);
        }
#pragma unroll
        for (int it = 0; it < 2; it++) {          // B1/B3: 64 rows x 64 halves
            int id = it * 256 + tid;
            int r = id >> 3, c = id & 7;
            uint32_t so = (uint32_t)(r * AK) * 2 + c * 16;
            const size_t go = (size_t)r * EMB + k0 + c * 8;
            cp16(st + A_T_H * 2 + so,           gB1 + go);
            cp16(st + (A_T_H + B_T_H) * 2 + so, gB3 + go);
        }
        CP_COMMIT();
    };

    float accZ[2][4][4], accG[2][4][4];
#pragma unroll
    for (int i = 0; i < 2; i++)
#pragma unroll
        for (int j = 0; j < 4; j++)
#pragma unroll
            for (int r = 0; r < 4; r++) { accZ[i][j][r] = 0.f; accG[i][j][r] = 0.f; }

#pragma unroll
    for (int p = 0; p < STG1 - 1; p++) load_stage(p, p);

    for (int kb = 0; kb < KB1; kb++) {
        asm volatile("cp.async.wait_group %0;" :: "n"(STG1 - 2) : "memory");
        __syncthreads();
        uint32_t stA = sbase + (uint32_t)(kb % STG1) * ST1H * 2;
        uint32_t stB1 = stA + A_T_H * 2;
        uint32_t stB3 = stA + (A_T_H + B_T_H) * 2;
#pragma unroll
        for (int ks = 0; ks < 4; ks++) {
            uint32_t ko = ks * 32;                // 16 halves per ks
            uint32_t a[2][4], b1[4], b3[4];
#pragma unroll
            for (int i = 0; i < 2; i++) ldsm4(a[i], stA + aoff[i] + ko);
            ldsm4(b1, stB1 + boff[0] + ko);
            ldsm4(b3, stB3 + boff[0] + ko);
#pragma unroll
            for (int i = 0; i < 2; i++) {
                mma16(accZ[i][0], a[i], b1);
                mma16(accZ[i][1], a[i], b1 + 2);
                mma16(accG[i][0], a[i], b3);
                mma16(accG[i][1], a[i], b3 + 2);
            }
            ldsm4(b1, stB1 + boff[1] + ko);
            ldsm4(b3, stB3 + boff[1] + ko);
#pragma unroll
            for (int i = 0; i < 2; i++) {
                mma16(accZ[i][2], a[i], b1);
                mma16(accZ[i][3], a[i], b1 + 2);
                mma16(accG[i][2], a[i], b3);
                mma16(accG[i][3], a[i], b3 + 2);
            }
        }
        if (kb + STG1 - 1 < KB1) load_stage(kb + STG1 - 1, (kb + STG1 - 1) % STG1);
        else CP_COMMIT();
    }

    __half* gH = g_h + (size_t)ho * HID + n0;
#pragma unroll
    for (int i = 0; i < 2; i++) {
        int r = wm * 32 + i * 16 + grp;
#pragma unroll
        for (int j = 0; j < 4; j++) {
            int c = wn * 32 + j * 8 + 2 * q;
            float h[4];
#pragma unroll
            for (int t2 = 0; t2 < 4; t2++) {
                float z = accZ[i][j][t2];
                float g = accG[i][j][t2];
                h[t2] = (z / (1.f + __expf(-z))) * g;
            }
            __half2 lo = __floats2half2_rn(h[0], h[1]);
            __half2 hi = __floats2half2_rn(h[2], h[3]);
            *(uint32_t*)(gH + (size_t)r * HID + c)       = *(uint32_t*)&lo;
            *(uint32_t*)(gH + (size_t)(r + 8) * HID + c) = *(uint32_t*)&hi;
        }
    }
}

// ===================== GEMM2: out += gate * (H @ W2) =====================
#define ST2H  (A_T_H + B_T_H)   // 13824 halves = 27648 B
#define STG2  4
#define KB2   (HID / 64)        // 44

__global__ void __launch_bounds__(256, 2) k_mma2(float* __restrict__ out) {
    extern __shared__ __half smh[];
    int e = blockIdx.z;
    int cnt = g_cnt[e];
    int m0 = blockIdx.y * 128;
    if (m0 >= cnt) return;
    int n0 = blockIdx.x * 64;
    int tid = threadIdx.x, lane = tid & 31, wid = tid >> 5;
    int wm = wid >> 1, wn = wid & 1;
    int grp = lane >> 2, q = lane & 3;
    uint32_t sbase = s2u(smh);
    int ho = offp_of(e) + m0;

    uint32_t aoff[2], boff[2];
#pragma unroll
    for (int i = 0; i < 2; i++)
        aoff[i] = (uint32_t)(((wm * 32 + i * 16 + (lane & 15)) * AK + 8 * (lane >> 4)) * 2);
#pragma unroll
    for (int jp = 0; jp < 2; jp++)
        boff[jp] = (uint32_t)(((wn * 32 + jp * 16 + (lane & 7) + 8 * (lane >> 4)) * AK
                               + 8 * ((lane >> 3) & 1)) * 2);

    const __half* gA = g_h   + (size_t)ho * HID;
    const __half* gB = g_w2h + ((size_t)e * EMB + n0) * HID;

    auto load_stage = [&](int kb, int s) {
        uint32_t st = sbase + (uint32_t)s * ST2H * 2;
        int k0 = kb * 64;
#pragma unroll
        for (int it = 0; it < 4; it++) {
            int id = it * 256 + tid;
            int r = id >> 3, c = id & 7;
            cp16(st + (uint32_t)(r * AK) * 2 + c * 16, gA + (size_t)r * HID + k0 + c * 8);
        }
#pragma unroll
        for (int it = 0; it < 2; it++) {
            int id = it * 256 + tid;
            int r = id >> 3, c = id & 7;
            cp16(st + A_T_H * 2 + (uint32_t)(r * AK) * 2 + c * 16,
                 gB + (size_t)r * HID + k0 + c * 8);
        }
        CP_COMMIT();
    };

    float acc[2][4][4];
#pragma unroll
    for (int i = 0; i < 2; i++)
#pragma unroll
        for (int j = 0; j < 4; j++)
#pragma unroll
            for (int r = 0; r < 4; r++) acc[i][j][r] = 0.f;

#pragma unroll
    for (int p = 0; p < STG2 - 1; p++) load_stage(p, p);

    for (int kb = 0; kb < KB2; kb++) {
        asm volatile("cp.async.wait_group %0;" :: "n"(STG2 - 2) : "memory");
        __syncthreads();
        uint32_t stA = sbase + (uint32_t)(kb % STG2) * ST2H * 2;
        uint32_t stB = stA + A_T_H * 2;
#pragma unroll
        for (int ks = 0; ks < 4; ks++) {
            uint32_t ko = ks * 32;
            uint32_t a[2][4], b[2][4];
#pragma unroll
            for (int i = 0; i < 2; i++)  ldsm4(a[i], stA + aoff[i] + ko);
#pragma unroll
            for (int jp = 0; jp < 2; jp++) ldsm4(b[jp], stB + boff[jp] + ko);
#pragma unroll
            for (int i = 0; i < 2; i++)
#pragma unroll
                for (int jp = 0; jp < 2; jp++) {
                    mma16(acc[i][jp * 2],     a[i], b[jp]);
                    mma16(acc[i][jp * 2 + 1], a[i], b[jp] + 2);
                }
        }
        if (kb + STG2 - 1 < KB2) load_stage(kb + STG2 - 1, (kb + STG2 - 1) % STG2);
        else CP_COMMIT();
    }

#pragma unroll
    for (int i = 0; i < 2; i++) {
        int r = wm * 32 + i * 16 + grp;
        int row0 = m0 + r, row1 = row0 + 8;
        bool act0 = row0 < cnt, act1 = row1 < cnt;
        int   t0 = act0 ? g_tok[e][row0] : 0;
        int   t1 = act1 ? g_tok[e][row1] : 0;
        float gt0 = act0 ? g_gate[e][row0] : 0.f;
        float gt1 = act1 ? g_gate[e][row1] : 0.f;
        float* o0 = out + (size_t)t0 * EMB + n0;
        float* o1 = out + (size_t)t1 * EMB + n0;
#pragma unroll
        for (int j = 0; j < 4; j++) {
            int c = wn * 32 + j * 8 + 2 * q;
            if (act0) {
                atomicAdd(&o0[c],     gt0 * acc[i][j][0]);
                atomicAdd(&o0[c + 1], gt0 * acc[i][j][1]);
            }
            if (act1) {
                atomicAdd(&o1[c],     gt1 * acc[i][j][2]);
                atomicAdd(&o1[c + 1], gt1 * acc[i][j][3]);
            }
        }
    }
}

// ===================== launcher =====================
extern "C" void kernel_launch(void* const* d_in, const int* in_sizes, int n_in,
                              void* d_out, int out_size) {
    const float* x  = (const float*)d_in[0];
    const float* wr = (const float*)d_in[1];
    const float* w1 = (const float*)d_in[2];
    const float* w3 = (const float*)d_in[3];
    const float* w2 = (const float*)d_in[4];
    float* out = (float*)d_out;

    const int SM1 = STG1 * ST1H * 2;   // 110592
    const int SM2 = STG2 * ST2H * 2;   // 110592
    cudaFuncSetAttribute(k_mma1, cudaFuncAttributeMaxDynamicSharedMemorySize, SM1);
    cudaFuncSetAttribute(k_mma2, cudaFuncAttributeMaxDynamicSharedMemorySize, SM2);

    k_roundT<<<dim3(HID / 32, EMB / 32, 3 * NE), dim3(32, 8)>>>(w1, w3, w2);
    k_router<<<NTOK / 8, 256>>>(x, wr);
    k_gather<<<dim3(NTOK / 16, NE), 256>>>(x);

    k_mma1<<<dim3(HID / 64, NTOK / 128, NE), 256, SM1>>>();

    cudaMemsetAsync(out, 0, (size_t)out_size * sizeof(float));
    k_mma2<<<dim3(EMB / 64, NTOK / 128, NE), 256, SM2>>>(out);
}

// round 12
// speedup vs baseline: 2.0258x; 1.0484x over previous
#include <cuda_runtime.h>
#include <cuda_fp16.h>
#include <cstdint>
#include <math.h>

#define NTOK 4096
#define EMB  1024
#define HID  2816
#define NE   8
#define MAXPAD 9216

// ===================== device scratch =====================
__device__ int   g_cnt[NE];
__device__ int   g_tok[NE][NTOK];
__device__ float g_gate[NE][NTOK];

__device__ __half g_xp[(size_t)MAXPAD * EMB];
__device__ __half g_h [(size_t)MAXPAD * HID];
__device__ __half g_w1h[(size_t)NE * HID * EMB];   // [e][n][k]
__device__ __half g_w3h[(size_t)NE * HID * EMB];
__device__ __half g_w2h[(size_t)NE * EMB * HID];   // [e][n=EMB][k=HID]

// ===================== helpers =====================
__device__ __forceinline__ void mma16(float* c, const uint32_t* a, const uint32_t* b) {
    asm volatile("mma.sync.aligned.m16n8k16.row.col.f32.f16.f16.f32 "
        "{%0,%1,%2,%3}, {%4,%5,%6,%7}, {%8,%9}, {%0,%1,%2,%3};"
        : "+f"(c[0]), "+f"(c[1]), "+f"(c[2]), "+f"(c[3])
        : "r"(a[0]), "r"(a[1]), "r"(a[2]), "r"(a[3]), "r"(b[0]), "r"(b[1]));
}
__device__ __forceinline__ void ldsm4(uint32_t* r, uint32_t addr) {
    asm volatile("ldmatrix.sync.aligned.m8n8.x4.shared.b16 {%0,%1,%2,%3}, [%4];"
        : "=r"(r[0]), "=r"(r[1]), "=r"(r[2]), "=r"(r[3]) : "r"(addr));
}
__device__ __forceinline__ uint32_t s2u(const void* p) {
    uint32_t a;
    asm("{ .reg .u64 t; cvta.to.shared.u64 t, %1; cvt.u32.u64 %0, t; }" : "=r"(a) : "l"(p));
    return a;
}
__device__ __forceinline__ void cp16(uint32_t dst, const void* src) {
    asm volatile("cp.async.cg.shared.global [%0], [%1], 16;" :: "r"(dst), "l"(src));
}
#define CP_COMMIT() asm volatile("cp.async.commit_group;" ::: "memory")

__device__ __forceinline__ int offp_of(int e) {
    int o = 0;
    for (int i = 0; i < NE; i++) if (i < e) o += (g_cnt[i] + 127) & ~127;
    return o;
}

// ===== fused: fp16-convert + transpose weights to [e][n][k], reset cnt =====
__global__ void k_roundT(const float* __restrict__ w1,
                         const float* __restrict__ w3,
                         const float* __restrict__ w2) {
    __shared__ float t[32][33];
    int which = blockIdx.z / NE, e = blockIdx.z % NE;
    if (which == 0 && blockIdx.x == 0 && blockIdx.y == 0 &&
        threadIdx.y == 0 && threadIdx.x < NE) g_cnt[threadIdx.x] = 0;

    const float* in; __half* outp; int K, N, nt, kt;
    if (which < 2) {
        in = ((which == 0) ? w1 : w3) + (size_t)e * EMB * HID;
        outp = ((which == 0) ? g_w1h : g_w3h) + (size_t)e * HID * EMB;
        K = EMB; N = HID; nt = blockIdx.x; kt = blockIdx.y;
    } else {
        in = w2 + (size_t)e * HID * EMB;
        outp = g_w2h + (size_t)e * EMB * HID;
        K = HID; N = EMB; kt = blockIdx.x; nt = blockIdx.y;
    }
    int tx = threadIdx.x, ty = threadIdx.y;
#pragma unroll
    for (int i = 0; i < 4; i++)
        t[ty + 8 * i][tx] = in[(size_t)(kt * 32 + ty + 8 * i) * N + nt * 32 + tx];
    __syncthreads();
#pragma unroll
    for (int i = 0; i < 4; i++)
        outp[(size_t)(nt * 32 + ty + 8 * i) * K + kt * 32 + tx] =
            __float2half_rn(t[tx][ty + 8 * i]);
}

// ===================== router =====================
__global__ void k_router(const float* __restrict__ x, const float* __restrict__ wr) {
    int t    = blockIdx.x * (blockDim.x >> 5) + (threadIdx.x >> 5);
    int lane = threadIdx.x & 31;
    if (t >= NTOK) return;
    const float* xr = x + (size_t)t * EMB;
    float acc[NE];
#pragma unroll
    for (int e = 0; e < NE; e++) acc[e] = 0.f;
    for (int i = lane; i < EMB; i += 32) {
        float xv = xr[i];
#pragma unroll
        for (int e = 0; e < NE; e++) acc[e] += xv * wr[i * NE + e];
    }
#pragma unroll
    for (int e = 0; e < NE; e++)
#pragma unroll
        for (int o = 16; o > 0; o >>= 1) acc[e] += __shfl_xor_sync(0xffffffffu, acc[e], o);
    if (lane == 0) {
        int i0 = 0; float v0 = acc[0];
#pragma unroll
        for (int e = 1; e < NE; e++) if (acc[e] > v0) { v0 = acc[e]; i0 = e; }
        int i1 = -1; float v1 = -3.4e38f;
#pragma unroll
        for (int e = 0; e < NE; e++) if (e != i0 && acc[e] > v1) { v1 = acc[e]; i1 = e; }
        float z  = expf(v1 - v0);
        float p0 = 1.f / (1.f + z);
        float p1 = z  / (1.f + z);
        int s0 = atomicAdd(&g_cnt[i0], 1);
        g_tok[i0][s0] = t; g_gate[i0][s0] = p0;
        int s1 = atomicAdd(&g_cnt[i1], 1);
        g_tok[i1][s1] = t; g_gate[i1][s1] = p1;
    }
}

// ===================== gather -> fp16 ====================
__global__ void k_gather(const float* __restrict__ x) {
    int e = blockIdx.y; int cnt = g_cnt[e];
    int m0 = blockIdx.x * 16;
    int padded = (cnt + 127) & ~127;
    if (m0 >= padded) return;
    __half* dst = g_xp + (size_t)(offp_of(e) + m0) * EMB;
    for (int idx = threadIdx.x; idx < 16 * 128; idx += 256) {
        int r = idx >> 7, j = idx & 127;
        int gm = m0 + r;
        uint4 o = make_uint4(0, 0, 0, 0);
        if (gm < cnt) {
            const float4* src = (const float4*)(x + (size_t)g_tok[e][gm] * EMB) + j * 2;
            float4 v0 = src[0], v1 = src[1];
            __half2 h0 = __floats2half2_rn(v0.x, v0.y);
            __half2 h1 = __floats2half2_rn(v0.z, v0.w);
            __half2 h2 = __floats2half2_rn(v1.x, v1.y);
            __half2 h3 = __floats2half2_rn(v1.z, v1.w);
            o = make_uint4(*(uint32_t*)&h0, *(uint32_t*)&h1,
                           *(uint32_t*)&h2, *(uint32_t*)&h3);
        }
        ((uint4*)(dst + (size_t)r * EMB))[j] = o;
    }
}

// ===================== GEMM1: H = silu(X@W1)*(X@W3) =====================
// CTA tile 128(M)x64(N)x64(K), 8 warps (4x2), warp tile 32x32, 2 CTAs/SM
#define AK    72
#define A_T_H (128 * AK)
#define B_T_H (64 * AK)
#define ST1H  (A_T_H + 2 * B_T_H)
#define STG1  3
#define KB1   (EMB / 64)            // 16

__global__ void __launch_bounds__(256, 2) k_mma1() {
    extern __shared__ __half smh[];
    int e = blockIdx.z;
    int cnt = g_cnt[e];
    int m0 = blockIdx.y * 128;
    if (m0 >= cnt) return;
    int n0 = blockIdx.x * 64;
    int tid = threadIdx.x, lane = tid & 31, wid = tid >> 5;
    int wm = wid >> 1, wn = wid & 1;
    int grp = lane >> 2, q = lane & 3;
    uint32_t sbase = s2u(smh);
    int ho = offp_of(e) + m0;

    uint32_t aoff[2], boff[2];
#pragma unroll
    for (int i = 0; i < 2; i++)
        aoff[i] = (uint32_t)(((wm * 32 + i * 16 + (lane & 15)) * AK + 8 * (lane >> 4)) * 2);
#pragma unroll
    for (int jp = 0; jp < 2; jp++)
        boff[jp] = (uint32_t)(((wn * 32 + jp * 16 + (lane & 7) + 8 * (lane >> 4)) * AK
                               + 8 * ((lane >> 3) & 1)) * 2);

    const __half* gA  = g_xp  + (size_t)ho * EMB;
    const __half* gB1 = g_w1h + ((size_t)e * HID + n0) * EMB;
    const __half* gB3 = g_w3h + ((size_t)e * HID + n0) * EMB;

    auto load_stage = [&](int kb, int s) {
        uint32_t st = sbase + (uint32_t)s * ST1H * 2;
        int k0 = kb * 64;
#pragma unroll
        for (int it = 0; it < 4; it++) {
            int id = it * 256 + tid;
            int r = id >> 3, c = id & 7;
            cp16(st + (uint32_t)(r * AK) * 2 + c * 16, gA + (size_t)r * EMB + k0 + c * 8);
        }
#pragma unroll
        for (int it = 0; it < 2; it++) {
            int id = it * 256 + tid;
            int r = id >> 3, c = id & 7;
            uint32_t so = (uint32_t)(r * AK) * 2 + c * 16;
            const size_t go = (size_t)r * EMB + k0 + c * 8;
            cp16(st + A_T_H * 2 + so,           gB1 + go);
            cp16(st + (A_T_H + B_T_H) * 2 + so, gB3 + go);
        }
        CP_COMMIT();
    };

    float accZ[2][4][4], accG[2][4][4];
#pragma unroll
    for (int i = 0; i < 2; i++)
#pragma unroll
        for (int j = 0; j < 4; j++)
#pragma unroll
            for (int r = 0; r < 4; r++) { accZ[i][j][r] = 0.f; accG[i][j][r] = 0.f; }

#pragma unroll
    for (int p = 0; p < STG1 - 1; p++) load_stage(p, p);

#pragma unroll
    for (int kb = 0; kb < KB1; kb++) {
        asm volatile("cp.async.wait_group %0;" :: "n"(STG1 - 2) : "memory");
        __syncthreads();
        uint32_t stA = sbase + (uint32_t)(kb % STG1) * ST1H * 2;
        uint32_t stB1 = stA + A_T_H * 2;
        uint32_t stB3 = stA + (A_T_H + B_T_H) * 2;
#pragma unroll
        for (int ks = 0; ks < 4; ks++) {
            uint32_t ko = ks * 32;
            uint32_t a[2][4], b1[4], b3[4];
#pragma unroll
            for (int i = 0; i < 2; i++) ldsm4(a[i], stA + aoff[i] + ko);
            ldsm4(b1, stB1 + boff[0] + ko);
            ldsm4(b3, stB3 + boff[0] + ko);
#pragma unroll
            for (int i = 0; i < 2; i++) {
                mma16(accZ[i][0], a[i], b1);
                mma16(accZ[i][1], a[i], b1 + 2);
                mma16(accG[i][0], a[i], b3);
                mma16(accG[i][1], a[i], b3 + 2);
            }
            ldsm4(b1, stB1 + boff[1] + ko);
            ldsm4(b3, stB3 + boff[1] + ko);
#pragma unroll
            for (int i = 0; i < 2; i++) {
                mma16(accZ[i][2], a[i], b1);
                mma16(accZ[i][3], a[i], b1 + 2);
                mma16(accG[i][2], a[i], b3);
                mma16(accG[i][3], a[i], b3 + 2);
            }
        }
        if (kb + STG1 - 1 < KB1) load_stage(kb + STG1 - 1, (kb + STG1 - 1) % STG1);
        else CP_COMMIT();
    }

    __half* gH = g_h + (size_t)ho * HID + n0;
#pragma unroll
    for (int i = 0; i < 2; i++) {
        int r = wm * 32 + i * 16 + grp;
#pragma unroll
        for (int j = 0; j < 4; j++) {
            int c = wn * 32 + j * 8 + 2 * q;
            float h[4];
#pragma unroll
            for (int t2 = 0; t2 < 4; t2++) {
                float z = accZ[i][j][t2];
                float g = accG[i][j][t2];
                h[t2] = (z / (1.f + __expf(-z))) * g;
            }
            __half2 lo = __floats2half2_rn(h[0], h[1]);
            __half2 hi = __floats2half2_rn(h[2], h[3]);
            *(uint32_t*)(gH + (size_t)r * HID + c)       = *(uint32_t*)&lo;
            *(uint32_t*)(gH + (size_t)(r + 8) * HID + c) = *(uint32_t*)&hi;
        }
    }
}

// ===================== GEMM2: out += gate * (H @ W2) =====================
#define ST2H  (A_T_H + B_T_H)
#define STG2  4
#define KB2   (HID / 64)        // 44

__global__ void __launch_bounds__(256, 2) k_mma2(float* __restrict__ out) {
    extern __shared__ __half smh[];
    int e = blockIdx.z;
    int cnt = g_cnt[e];
    int m0 = blockIdx.y * 128;
    if (m0 >= cnt) return;
    int n0 = blockIdx.x * 64;
    int tid = threadIdx.x, lane = tid & 31, wid = tid >> 5;
    int wm = wid >> 1, wn = wid & 1;
    int grp = lane >> 2, q = lane & 3;
    uint32_t sbase = s2u(smh);
    int ho = offp_of(e) + m0;

    uint32_t aoff[2], boff[2];
#pragma unroll
    for (int i = 0; i < 2; i++)
        aoff[i] = (uint32_t)(((wm * 32 + i * 16 + (lane & 15)) * AK + 8 * (lane >> 4)) * 2);
#pragma unroll
    for (int jp = 0; jp < 2; jp++)
        boff[jp] = (uint32_t)(((wn * 32 + jp * 16 + (lane & 7) + 8 * (lane >> 4)) * AK
                               + 8 * ((lane >> 3) & 1)) * 2);

    const __half* gA = g_h   + (size_t)ho * HID;
    const __half* gB = g_w2h + ((size_t)e * EMB + n0) * HID;

    auto load_stage = [&](int kb, int s) {
        uint32_t st = sbase + (uint32_t)s * ST2H * 2;
        int k0 = kb * 64;
#pragma unroll
        for (int it = 0; it < 4; it++) {
            int id = it * 256 + tid;
            int r = id >> 3, c = id & 7;
            cp16(st + (uint32_t)(r * AK) * 2 + c * 16, gA + (size_t)r * HID + k0 + c * 8);
        }
#pragma unroll
        for (int it = 0; it < 2; it++) {
            int id = it * 256 + tid;
            int r = id >> 3, c = id & 7;
            cp16(st + A_T_H * 2 + (uint32_t)(r * AK) * 2 + c * 16,
                 gB + (size_t)r * HID + k0 + c * 8);
        }
        CP_COMMIT();
    };

    float acc[2][4][4];
#pragma unroll
    for (int i = 0; i < 2; i++)
#pragma unroll
        for (int j = 0; j < 4; j++)
#pragma unroll
            for (int r = 0; r < 4; r++) acc[i][j][r] = 0.f;

#pragma unroll
    for (int p = 0; p < STG2 - 1; p++) load_stage(p, p);

    for (int kb = 0; kb < KB2; kb++) {
        asm volatile("cp.async.wait_group %0;" :: "n"(STG2 - 2) : "memory");
        __syncthreads();
        uint32_t stA = sbase + (uint32_t)(kb % STG2) * ST2H * 2;
        uint32_t stB = stA + A_T_H * 2;

        // software-pipelined fragments across ks
        uint32_t a[2][2][4], b[2][2][4];
#pragma unroll
        for (int i = 0; i < 2; i++)  ldsm4(a[0][i], stA + aoff[i]);
#pragma unroll
        for (int jp = 0; jp < 2; jp++) ldsm4(b[0][jp], stB + boff[jp]);
#pragma unroll
        for (int ks = 0; ks < 4; ks++) {
            int cur = ks & 1, nxt = cur ^ 1;
            if (ks < 3) {
                uint32_t ko = (uint32_t)(ks + 1) * 32;
#pragma unroll
                for (int i = 0; i < 2; i++)  ldsm4(a[nxt][i], stA + aoff[i] + ko);
#pragma unroll
                for (int jp = 0; jp < 2; jp++) ldsm4(b[nxt][jp], stB + boff[jp] + ko);
            }
#pragma unroll
            for (int i = 0; i < 2; i++)
#pragma unroll
                for (int jp = 0; jp < 2; jp++) {
                    mma16(acc[i][jp * 2],     a[cur][i], b[cur][jp]);
                    mma16(acc[i][jp * 2 + 1], a[cur][i], b[cur][jp] + 2);
                }
        }
        if (kb + STG2 - 1 < KB2) load_stage(kb + STG2 - 1, (kb + STG2 - 1) % STG2);
        else CP_COMMIT();
    }

#pragma unroll
    for (int i = 0; i < 2; i++) {
        int r = wm * 32 + i * 16 + grp;
        int row0 = m0 + r, row1 = row0 + 8;
        bool act0 = row0 < cnt, act1 = row1 < cnt;
        int   t0 = act0 ? g_tok[e][row0] : 0;
        int   t1 = act1 ? g_tok[e][row1] : 0;
        float gt0 = act0 ? g_gate[e][row0] : 0.f;
        float gt1 = act1 ? g_gate[e][row1] : 0.f;
        float* o0 = out + (size_t)t0 * EMB + n0;
        float* o1 = out + (size_t)t1 * EMB + n0;
#pragma unroll
        for (int j = 0; j < 4; j++) {
            int c = wn * 32 + j * 8 + 2 * q;
            if (act0) {
                atomicAdd(&o0[c],     gt0 * acc[i][j][0]);
                atomicAdd(&o0[c + 1], gt0 * acc[i][j][1]);
            }
            if (act1) {
                atomicAdd(&o1[c],     gt1 * acc[i][j][2]);
                atomicAdd(&o1[c + 1], gt1 * acc[i][j][3]);
            }
        }
    }
}

// ===================== launcher =====================
extern "C" void kernel_launch(void* const* d_in, const int* in_sizes, int n_in,
                              void* d_out, int out_size) {
    const float* x  = (const float*)d_in[0];
    const float* wr = (const float*)d_in[1];
    const float* w1 = (const float*)d_in[2];
    const float* w3 = (const float*)d_in[3];
    const float* w2 = (const float*)d_in[4];
    float* out = (float*)d_out;

    const int SM1 = STG1 * ST1H * 2;   // 110592
    const int SM2 = STG2 * ST2H * 2;   // 110592
    cudaFuncSetAttribute(k_mma1, cudaFuncAttributeMaxDynamicSharedMemorySize, SM1);
    cudaFuncSetAttribute(k_mma2, cudaFuncAttributeMaxDynamicSharedMemorySize, SM2);

    k_roundT<<<dim3(HID / 32, EMB / 32, 3 * NE), dim3(32, 8)>>>(w1, w3, w2);
    k_router<<<NTOK / 8, 256>>>(x, wr);
    k_gather<<<dim3(NTOK / 16, NE), 256>>>(x);

    k_mma1<<<dim3(HID / 64, NTOK / 128, NE), 256, SM1>>>();

    cudaMemsetAsync(out, 0, (size_t)out_size * sizeof(float));
    k_mma2<<<dim3(EMB / 64, NTOK / 128, NE), 256, SM2>>>(out);
}

// round 15
// speedup vs baseline: 2.1693x; 1.0708x over previous
#include <cuda_runtime.h>
#include <cuda_fp16.h>
#include <cstdint>
#include <math.h>

#define NTOK 4096
#define EMB  1024
#define HID  2816
#define NE   8
#define MAXPAD 9216

// ===================== device scratch =====================
__device__ int   g_cnt[NE];
__device__ int   g_tok[NE][NTOK];
__device__ float g_gate[NE][NTOK];

__device__ __half g_xp[(size_t)MAXPAD * EMB];
__device__ __half g_h [(size_t)MAXPAD * HID];
__device__ __half g_w1h[(size_t)NE * HID * EMB];   // [e][n][k]
__device__ __half g_w3h[(size_t)NE * HID * EMB];
__device__ __half g_w2h[(size_t)NE * EMB * HID];   // [e][n=EMB][k=HID]

// ===================== helpers =====================
__device__ __forceinline__ void mma16(float* c, const uint32_t* a, const uint32_t* b) {
    asm volatile("mma.sync.aligned.m16n8k16.row.col.f32.f16.f16.f32 "
        "{%0,%1,%2,%3}, {%4,%5,%6,%7}, {%8,%9}, {%0,%1,%2,%3};"
        : "+f"(c[0]), "+f"(c[1]), "+f"(c[2]), "+f"(c[3])
        : "r"(a[0]), "r"(a[1]), "r"(a[2]), "r"(a[3]), "r"(b[0]), "r"(b[1]));
}
__device__ __forceinline__ void ldsm4(uint32_t* r, uint32_t addr) {
    asm volatile("ldmatrix.sync.aligned.m8n8.x4.shared.b16 {%0,%1,%2,%3}, [%4];"
        : "=r"(r[0]), "=r"(r[1]), "=r"(r[2]), "=r"(r[3]) : "r"(addr));
}
__device__ __forceinline__ uint32_t s2u(const void* p) {
    uint32_t a;
    asm("{ .reg .u64 t; cvta.to.shared.u64 t, %1; cvt.u32.u64 %0, t; }" : "=r"(a) : "l"(p));
    return a;
}
__device__ __forceinline__ void cp16(uint32_t dst, const void* src) {
    asm volatile("cp.async.cg.shared.global [%0], [%1], 16;" :: "r"(dst), "l"(src));
}
#define CP_COMMIT() asm volatile("cp.async.commit_group;" ::: "memory")

__device__ __forceinline__ int offp_of(int e) {
    int o = 0;
    for (int i = 0; i < NE; i++) if (i < e) o += (g_cnt[i] + 127) & ~127;
    return o;
}

// ===== fused: fp16-convert + transpose weights to [e][n][k], reset cnt =====
__global__ void k_roundT(const float* __restrict__ w1,
                         const float* __restrict__ w3,
                         const float* __restrict__ w2) {
    __shared__ float t[32][33];
    int which = blockIdx.z / NE, e = blockIdx.z % NE;
    if (which == 0 && blockIdx.x == 0 && blockIdx.y == 0 &&
        threadIdx.y == 0 && threadIdx.x < NE) g_cnt[threadIdx.x] = 0;

    const float* in; __half* outp; int K, N, nt, kt;
    if (which < 2) {
        in = ((which == 0) ? w1 : w3) + (size_t)e * EMB * HID;
        outp = ((which == 0) ? g_w1h : g_w3h) + (size_t)e * HID * EMB;
        K = EMB; N = HID; nt = blockIdx.x; kt = blockIdx.y;
    } else {
        in = w2 + (size_t)e * HID * EMB;
        outp = g_w2h + (size_t)e * EMB * HID;
        K = HID; N = EMB; kt = blockIdx.x; nt = blockIdx.y;
    }
    int tx = threadIdx.x, ty = threadIdx.y;
#pragma unroll
    for (int i = 0; i < 4; i++)
        t[ty + 8 * i][tx] = in[(size_t)(kt * 32 + ty + 8 * i) * N + nt * 32 + tx];
    __syncthreads();
#pragma unroll
    for (int i = 0; i < 4; i++)
        outp[(size_t)(nt * 32 + ty + 8 * i) * K + kt * 32 + tx] =
            __float2half_rn(t[tx][ty + 8 * i]);
}

// ===================== router =====================
__global__ void k_router(const float* __restrict__ x, const float* __restrict__ wr) {
    int t    = blockIdx.x * (blockDim.x >> 5) + (threadIdx.x >> 5);
    int lane = threadIdx.x & 31;
    if (t >= NTOK) return;
    const float* xr = x + (size_t)t * EMB;
    float acc[NE];
#pragma unroll
    for (int e = 0; e < NE; e++) acc[e] = 0.f;
    for (int i = lane; i < EMB; i += 32) {
        float xv = xr[i];
#pragma unroll
        for (int e = 0; e < NE; e++) acc[e] += xv * wr[i * NE + e];
    }
#pragma unroll
    for (int e = 0; e < NE; e++)
#pragma unroll
        for (int o = 16; o > 0; o >>= 1) acc[e] += __shfl_xor_sync(0xffffffffu, acc[e], o);
    if (lane == 0) {
        int i0 = 0; float v0 = acc[0];
#pragma unroll
        for (int e = 1; e < NE; e++) if (acc[e] > v0) { v0 = acc[e]; i0 = e; }
        int i1 = -1; float v1 = -3.4e38f;
#pragma unroll
        for (int e = 0; e < NE; e++) if (e != i0 && acc[e] > v1) { v1 = acc[e]; i1 = e; }
        float z  = expf(v1 - v0);
        float p0 = 1.f / (1.f + z);
        float p1 = z  / (1.f + z);
        int s0 = atomicAdd(&g_cnt[i0], 1);
        g_tok[i0][s0] = t; g_gate[i0][s0] = p0;
        int s1 = atomicAdd(&g_cnt[i1], 1);
        g_tok[i1][s1] = t; g_gate[i1][s1] = p1;
    }
}

// ===================== gather -> fp16 ====================
__global__ void k_gather(const float* __restrict__ x) {
    int e = blockIdx.y; int cnt = g_cnt[e];
    int m0 = blockIdx.x * 16;
    int padded = (cnt + 127) & ~127;
    if (m0 >= padded) return;
    __half* dst = g_xp + (size_t)(offp_of(e) + m0) * EMB;
    for (int idx = threadIdx.x; idx < 16 * 128; idx += 256) {
        int r = idx >> 7, j = idx & 127;
        int gm = m0 + r;
        uint4 o = make_uint4(0, 0, 0, 0);
        if (gm < cnt) {
            const float4* src = (const float4*)(x + (size_t)g_tok[e][gm] * EMB) + j * 2;
            float4 v0 = src[0], v1 = src[1];
            __half2 h0 = __floats2half2_rn(v0.x, v0.y);
            __half2 h1 = __floats2half2_rn(v0.z, v0.w);
            __half2 h2 = __floats2half2_rn(v1.x, v1.y);
            __half2 h3 = __floats2half2_rn(v1.z, v1.w);
            o = make_uint4(*(uint32_t*)&h0, *(uint32_t*)&h1,
                           *(uint32_t*)&h2, *(uint32_t*)&h3);
        }
        ((uint4*)(dst + (size_t)r * EMB))[j] = o;
    }
}

// ===================== GEMM1: H = silu(X@W1)*(X@W3) =====================
// CTA tile 128(M)x64(N)x64(K), 8 warps (4x2), warp tile 32x32, 2 CTAs/SM
#define AK    72
#define A_T_H (128 * AK)
#define B_T_H (64 * AK)
#define ST1H  (A_T_H + 2 * B_T_H)
#define STG1  3
#define KB1   (EMB / 64)            // 16

__global__ void __launch_bounds__(256, 2) k_mma1() {
    extern __shared__ __half smh[];
    int e = blockIdx.z;
    int cnt = g_cnt[e];
    int m0 = blockIdx.y * 128;
    if (m0 >= cnt) return;
    int n0 = blockIdx.x * 64;
    int tid = threadIdx.x, lane = tid & 31, wid = tid >> 5;
    int wm = wid >> 1, wn = wid & 1;
    int grp = lane >> 2, q = lane & 3;
    uint32_t sbase = s2u(smh);
    int ho = offp_of(e) + m0;

    uint32_t aoff[2], boff[2];
#pragma unroll
    for (int i = 0; i < 2; i++)
        aoff[i] = (uint32_t)(((wm * 32 + i * 16 + (lane & 15)) * AK + 8 * (lane >> 4)) * 2);
#pragma unroll
    for (int jp = 0; jp < 2; jp++)
        boff[jp] = (uint32_t)(((wn * 32 + jp * 16 + (lane & 7) + 8 * (lane >> 4)) * AK
                               + 8 * ((lane >> 3) & 1)) * 2);

    const __half* gA  = g_xp  + (size_t)ho * EMB;
    const __half* gB1 = g_w1h + ((size_t)e * HID + n0) * EMB;
    const __half* gB3 = g_w3h + ((size_t)e * HID + n0) * EMB;

    auto load_stage = [&](int kb, int s) {
        uint32_t st = sbase + (uint32_t)s * ST1H * 2;
        int k0 = kb * 64;
#pragma unroll
        for (int it = 0; it < 4; it++) {
            int id = it * 256 + tid;
            int r = id >> 3, c = id & 7;
            cp16(st + (uint32_t)(r * AK) * 2 + c * 16, gA + (size_t)r * EMB + k0 + c * 8);
        }
#pragma unroll
        for (int it = 0; it < 2; it++) {
            int id = it * 256 + tid;
            int r = id >> 3, c = id & 7;
            uint32_t so = (uint32_t)(r * AK) * 2 + c * 16;
            const size_t go = (size_t)r * EMB + k0 + c * 8;
            cp16(st + A_T_H * 2 + so,           gB1 + go);
            cp16(st + (A_T_H + B_T_H) * 2 + so, gB3 + go);
        }
        CP_COMMIT();
    };

    float accZ[2][4][4], accG[2][4][4];
#pragma unroll
    for (int i = 0; i < 2; i++)
#pragma unroll
        for (int j = 0; j < 4; j++)
#pragma unroll
            for (int r = 0; r < 4; r++) { accZ[i][j][r] = 0.f; accG[i][j][r] = 0.f; }

#pragma unroll
    for (int p = 0; p < STG1 - 1; p++) load_stage(p, p);

#pragma unroll
    for (int kb = 0; kb < KB1; kb++) {
        asm volatile("cp.async.wait_group %0;" :: "n"(STG1 - 2) : "memory");
        __syncthreads();
        uint32_t stA = sbase + (uint32_t)(kb % STG1) * ST1H * 2;
        uint32_t stB1 = stA + A_T_H * 2;
        uint32_t stB3 = stA + (A_T_H + B_T_H) * 2;
#pragma unroll
        for (int ks = 0; ks < 4; ks++) {
            uint32_t ko = ks * 32;
            uint32_t a[2][4], b1[4], b3[4];
#pragma unroll
            for (int i = 0; i < 2; i++) ldsm4(a[i], stA + aoff[i] + ko);
            ldsm4(b1, stB1 + boff[0] + ko);
            ldsm4(b3, stB3 + boff[0] + ko);
#pragma unroll
            for (int i = 0; i < 2; i++) {
                mma16(accZ[i][0], a[i], b1);
                mma16(accZ[i][1], a[i], b1 + 2);
                mma16(accG[i][0], a[i], b3);
                mma16(accG[i][1], a[i], b3 + 2);
            }
            ldsm4(b1, stB1 + boff[1] + ko);
            ldsm4(b3, stB3 + boff[1] + ko);
#pragma unroll
            for (int i = 0; i < 2; i++) {
                mma16(accZ[i][2], a[i], b1);
                mma16(accZ[i][3], a[i], b1 + 2);
                mma16(accG[i][2], a[i], b3);
                mma16(accG[i][3], a[i], b3 + 2);
            }
        }
        if (kb + STG1 - 1 < KB1) load_stage(kb + STG1 - 1, (kb + STG1 - 1) % STG1);
        else CP_COMMIT();
    }

    __half* gH = g_h + (size_t)ho * HID + n0;
#pragma unroll
    for (int i = 0; i < 2; i++) {
        int r = wm * 32 + i * 16 + grp;
#pragma unroll
        for (int j = 0; j < 4; j++) {
            int c = wn * 32 + j * 8 + 2 * q;
            float h[4];
#pragma unroll
            for (int t2 = 0; t2 < 4; t2++) {
                float z = accZ[i][j][t2];
                float g = accG[i][j][t2];
                h[t2] = (z / (1.f + __expf(-z))) * g;
            }
            __half2 lo = __floats2half2_rn(h[0], h[1]);
            __half2 hi = __floats2half2_rn(h[2], h[3]);
            *(uint32_t*)(gH + (size_t)r * HID + c)       = *(uint32_t*)&lo;
            *(uint32_t*)(gH + (size_t)(r + 8) * HID + c) = *(uint32_t*)&hi;
        }
    }
}

// ===================== GEMM2: out += gate * (H @ W2) =====================
// CTA tile 128(M)x128(N)x64(K), 8 warps (4x2), warp tile 32x64, 2 CTAs/SM
#define B2_T_H (128 * AK)               // 9216 halves
#define ST2H  (A_T_H + B2_T_H)          // 18432 halves = 36864 B
#define STG2  3
#define KB2   (HID / 64)                // 44

__global__ void __launch_bounds__(256, 2) k_mma2(float* __restrict__ out) {
    extern __shared__ __half smh[];
    int e = blockIdx.z;
    int cnt = g_cnt[e];
    int m0 = blockIdx.y * 128;
    if (m0 >= cnt) return;
    int n0 = blockIdx.x * 128;
    int tid = threadIdx.x, lane = tid & 31, wid = tid >> 5;
    int wm = wid >> 1, wn = wid & 1;      // 4 x 2: warp tile 32(M) x 64(N)
    int grp = lane >> 2, q = lane & 3;
    uint32_t sbase = s2u(smh);
    int ho = offp_of(e) + m0;

    uint32_t aoff[2], boff[4];
#pragma unroll
    for (int i = 0; i < 2; i++)
        aoff[i] = (uint32_t)(((wm * 32 + i * 16 + (lane & 15)) * AK + 8 * (lane >> 4)) * 2);
#pragma unroll
    for (int jp = 0; jp < 4; jp++)
        boff[jp] = (uint32_t)(((wn * 64 + jp * 16 + (lane & 7) + 8 * (lane >> 4)) * AK
                               + 8 * ((lane >> 3) & 1)) * 2);

    const __half* gA = g_h   + (size_t)ho * HID;
    const __half* gB = g_w2h + ((size_t)e * EMB + n0) * HID;

    auto load_stage = [&](int kb, int s) {
        uint32_t st = sbase + (uint32_t)s * ST2H * 2;
        int k0 = kb * 64;
#pragma unroll
        for (int it = 0; it < 4; it++) {
            int id = it * 256 + tid;
            int r = id >> 3, c = id & 7;
            uint32_t so = (uint32_t)(r * AK) * 2 + c * 16;
            cp16(st + so,              gA + (size_t)r * HID + k0 + c * 8);
            cp16(st + A_T_H * 2 + so,  gB + (size_t)r * HID + k0 + c * 8);
        }
        CP_COMMIT();
    };

    float acc[2][8][4];
#pragma unroll
    for (int i = 0; i < 2; i++)
#pragma unroll
        for (int j = 0; j < 8; j++)
#pragma unroll
            for (int r = 0; r < 4; r++) acc[i][j][r] = 0.f;

#pragma unroll
    for (int p = 0; p < STG2 - 1; p++) load_stage(p, p);

    for (int kb = 0; kb < KB2; kb++) {
        asm volatile("cp.async.wait_group %0;" :: "n"(STG2 - 2) : "memory");
        __syncthreads();
        uint32_t stA = sbase + (uint32_t)(kb % STG2) * ST2H * 2;
        uint32_t stB = stA + A_T_H * 2;
#pragma unroll
        for (int ks = 0; ks < 4; ks++) {
            uint32_t ko = ks * 32;
            uint32_t a[2][4], b[4];
#pragma unroll
            for (int i = 0; i < 2; i++) ldsm4(a[i], stA + aoff[i] + ko);
#pragma unroll
            for (int jp = 0; jp < 4; jp++) {
                ldsm4(b, stB + boff[jp] + ko);
#pragma unroll
                for (int i = 0; i < 2; i++) {
                    mma16(acc[i][jp * 2],     a[i], b);
                    mma16(acc[i][jp * 2 + 1], a[i], b + 2);
                }
            }
        }
        if (kb + STG2 - 1 < KB2)
            load_stage(kb + STG2 - 1, (kb + STG2 - 1) % STG2);
        else CP_COMMIT();
    }

#pragma unroll
    for (int i = 0; i < 2; i++) {
        int r = wm * 32 + i * 16 + grp;
        int row0 = m0 + r, row1 = row0 + 8;
        bool act0 = row0 < cnt, act1 = row1 < cnt;
        int   t0 = act0 ? g_tok[e][row0] : 0;
        int   t1 = act1 ? g_tok[e][row1] : 0;
        float gt0 = act0 ? g_gate[e][row0] : 0.f;
        float gt1 = act1 ? g_gate[e][row1] : 0.f;
        float* o0 = out + (size_t)t0 * EMB + n0;
        float* o1 = out + (size_t)t1 * EMB + n0;
#pragma unroll
        for (int j = 0; j < 8; j++) {
            int c = wn * 64 + j * 8 + 2 * q;
            if (act0) {
                atomicAdd(&o0[c],     gt0 * acc[i][j][0]);
                atomicAdd(&o0[c + 1], gt0 * acc[i][j][1]);
            }
            if (act1) {
                atomicAdd(&o1[c],     gt1 * acc[i][j][2]);
                atomicAdd(&o1[c + 1], gt1 * acc[i][j][3]);
            }
        }
    }
}

// ===================== launcher =====================
extern "C" void kernel_launch(void* const* d_in, const int* in_sizes, int n_in,
                              void* d_out, int out_size) {
    const float* x  = (const float*)d_in[0];
    const float* wr = (const float*)d_in[1];
    const float* w1 = (const float*)d_in[2];
    const float* w3 = (const float*)d_in[3];
    const float* w2 = (const float*)d_in[4];
    float* out = (float*)d_out;

    const int SM1 = STG1 * ST1H * 2;   // 110592
    const int SM2 = STG2 * ST2H * 2;   // 110592
    cudaFuncSetAttribute(k_mma1, cudaFuncAttributeMaxDynamicSharedMemorySize, SM1);
    cudaFuncSetAttribute(k_mma2, cudaFuncAttributeMaxDynamicSharedMemorySize, SM2);

    k_roundT<<<dim3(HID / 32, EMB / 32, 3 * NE), dim3(32, 8)>>>(w1, w3, w2);
    k_router<<<NTOK / 8, 256>>>(x, wr);
    k_gather<<<dim3(NTOK / 16, NE), 256>>>(x);

    k_mma1<<<dim3(HID / 64, NTOK / 128, NE), 256, SM1>>>();

    cudaMemsetAsync(out, 0, (size_t)out_size * sizeof(float));
    k_mma2<<<dim3(EMB / 128, NTOK / 128, NE), 256, SM2>>>(out);
}